// round 5
// baseline (speedup 1.0000x reference)
#include <cuda_runtime.h>
#include <math.h>

// ---------------- problem constants ----------------
constexpr int NU  = 40000;
constexpr int NI  = 40000;
constexpr int NT  = 80000;      // NU + NI
constexpr int D   = 128;
constexpr int EMP = 640000;
constexpr int EUI = 1600000;
constexpr int BSZ = 8192;
constexpr int BD  = BSZ * D;

// ---------------- device scratch (no allocs allowed) ----------------
__device__ float d_hu[NU * D];
__device__ float d_hi[NI * D];
__device__ float d_z0[NU * D];
__device__ float d_z1[NU * D];
__device__ float d_xA[NT * D];
__device__ float d_xB[NT * D];

__device__ int   d_mpcol[4 * EMP];
__device__ int   d_mpoff[4 * (NU + 1)];
__device__ int   d_mpcnt[4 * NU];     // dst counts
__device__ int   d_mpocnt[4 * NU];    // src counts
__device__ int   d_mpcur[4 * NU];
__device__ float d_oinv[4 * NU];
__device__ float d_iinv[4 * NU];

__device__ int   d_uicol[EUI];
__device__ int   d_uioff[NT + 1];
__device__ int   d_uicnt[NT];
__device__ int   d_uicur[NT];
__device__ float d_dinv[NT];

__device__ float d_S[12];     // attention score sums (2 per side-iter)
__device__ float d_pos[4];    // [0]=2*posdot sum U, [2]=2*posdot sum I
__device__ float d_n1u[BD], d_n2u[BD], d_n1i[BD], d_n2i[BD];
__device__ float d_embU[BD], d_embI[BD], d_embN[BD];
__device__ float d_alls[2 * BSZ];

// ---------------- helpers ----------------
__device__ __forceinline__ float warp_sum(float v) {
    #pragma unroll
    for (int d2 = 16; d2 > 0; d2 >>= 1) v += __shfl_down_sync(0xffffffffu, v, d2);
    return __shfl_sync(0xffffffffu, v, 0);
}
__device__ __forceinline__ float fast_tanh(float x) {
    float y; asm("tanh.approx.f32 %0, %1;" : "=f"(y) : "f"(x)); return y;
}

// ---------------- structure kernels ----------------
__global__ void k_count(const int* __restrict__ a, int n, int* __restrict__ cnt) {
    int i = blockIdx.x * blockDim.x + threadIdx.x, st = gridDim.x * blockDim.x;
    for (; i < n; i += st) atomicAdd(&cnt[a[i]], 1);
}
__global__ void k_inv_max1(const int* __restrict__ cnt, float* __restrict__ inv, int n) {
    int i = blockIdx.x * blockDim.x + threadIdx.x, st = gridDim.x * blockDim.x;
    for (; i < n; i += st) { int c = cnt[i]; inv[i] = rsqrtf((float)(c > 1 ? c : 1)); }
}
__global__ void k_inv_or0(const int* __restrict__ cnt, float* __restrict__ inv, int n) {
    int i = blockIdx.x * blockDim.x + threadIdx.x, st = gridDim.x * blockDim.x;
    for (; i < n; i += st) { int c = cnt[i]; inv[i] = (c > 0) ? rsqrtf((float)c) : 0.0f; }
}

// single-block chunked exclusive scan: off[0..n]; 1024 threads, 4 elems/thread/chunk
__global__ void k_scan(const int* __restrict__ cnt, int* __restrict__ off, int n) {
    __shared__ int wsum[32];
    __shared__ int carry_s;
    int t = threadIdx.x, lane = t & 31, wid = t >> 5;
    if (t == 0) { carry_s = 0; off[0] = 0; }
    __syncthreads();
    for (int base = 0; base < n; base += 4096) {
        int idx0 = base + t * 4;
        int v0 = (idx0 + 0 < n) ? cnt[idx0 + 0] : 0;
        int v1 = (idx0 + 1 < n) ? cnt[idx0 + 1] : 0;
        int v2 = (idx0 + 2 < n) ? cnt[idx0 + 2] : 0;
        int v3 = (idx0 + 3 < n) ? cnt[idx0 + 3] : 0;
        v1 += v0; v2 += v1; v3 += v2;
        int ts = v3, sc = ts;
        #pragma unroll
        for (int d2 = 1; d2 < 32; d2 <<= 1) {
            int x = __shfl_up_sync(0xffffffffu, sc, d2);
            if (lane >= d2) sc += x;
        }
        if (lane == 31) wsum[wid] = sc;
        __syncthreads();
        if (wid == 0) {
            int s2 = wsum[lane];
            #pragma unroll
            for (int d2 = 1; d2 < 32; d2 <<= 1) {
                int x = __shfl_up_sync(0xffffffffu, s2, d2);
                if (lane >= d2) s2 += x;
            }
            wsum[lane] = s2;
        }
        __syncthreads();
        int woff = wid ? wsum[wid - 1] : 0;
        int b0 = carry_s + woff + (sc - ts);
        if (idx0 + 0 < n) off[idx0 + 1] = b0 + v0;
        if (idx0 + 1 < n) off[idx0 + 2] = b0 + v1;
        if (idx0 + 2 < n) off[idx0 + 3] = b0 + v2;
        if (idx0 + 3 < n) off[idx0 + 4] = b0 + v3;
        __syncthreads();
        if (t == 0) carry_s += wsum[31];
        __syncthreads();
    }
}

__global__ void k_fill(const int* __restrict__ key, const int* __restrict__ val, int n,
                       const int* __restrict__ off, int* __restrict__ cur, int* __restrict__ col) {
    int i = blockIdx.x * blockDim.x + threadIdx.x, st = gridDim.x * blockDim.x;
    for (; i < n; i += st) {
        int k = key[i];
        col[off[k] + atomicAdd(&cur[k], 1)] = val[i];
    }
}

__global__ void k_copy4(const float4* __restrict__ s, float4* __restrict__ d, int n) {
    int i = blockIdx.x * blockDim.x + threadIdx.x, st = gridDim.x * blockDim.x;
    for (; i < n; i += st) d[i] = s[i];
}

// ---------------- normalized graph conv: z[w] = dinv[w]*sum_{c in adj(w)} sinv[c]*h[c] ----------------
__global__ void k_conv(const float4* __restrict__ h, const int* __restrict__ off,
                       const int* __restrict__ col, const float* __restrict__ sinv,
                       const float* __restrict__ dinv, float4* __restrict__ z, int n) {
    int w = (blockIdx.x * blockDim.x + threadIdx.x) >> 5;
    int lane = threadIdx.x & 31;
    if (w >= n) return;
    int s = off[w], e = off[w + 1];
    float ax = 0.f, ay = 0.f, az = 0.f, aw = 0.f;
    for (int k = s; k < e; k++) {
        int c = col[k];
        float wt = sinv[c];
        float4 v = h[c * 32 + lane];
        ax = fmaf(wt, v.x, ax); ay = fmaf(wt, v.y, ay);
        az = fmaf(wt, v.z, az); aw = fmaf(wt, v.w, aw);
    }
    float di = dinv[w];
    z[w * 32 + lane] = make_float4(ax * di, ay * di, az * di, aw * di);
}

// ---------------- semantic attention scores: S[p] += sum_n tanh(z_p[n]@W1+b1)@W2 ----------------
__global__ void k_att(const float* __restrict__ z0, const float* __restrict__ z1,
                      const float* __restrict__ W1, const float* __restrict__ b1,
                      const float* __restrict__ W2, float* __restrict__ S, int n) {
    extern __shared__ float sW1[];        // 128*128 floats, natural layout
    __shared__ float4 sz[8 * 32];
    __shared__ float red[128];
    int t = threadIdx.x;                  // 128 threads; t = hidden column j
    for (int i = t; i < D * D; i += 128) sW1[i] = W1[i];
    float bv = b1[t], w2v = W2[t];
    __syncthreads();
    float acc0 = 0.f, acc1 = 0.f;
    for (int nb = blockIdx.x * 8; nb < n; nb += gridDim.x * 8) {
        #pragma unroll
        for (int p = 0; p < 2; p++) {
            const float4* z4 = (const float4*)(p ? z1 : z0);
            __syncthreads();
            for (int q = t; q < 256; q += 128) {
                int row = nb + (q >> 5);
                sz[q] = (row < n) ? z4[row * 32 + (q & 31)] : make_float4(0.f, 0.f, 0.f, 0.f);
            }
            __syncthreads();
            float tv[8];
            #pragma unroll
            for (int m = 0; m < 8; m++) tv[m] = bv;
            #pragma unroll 4
            for (int k4 = 0; k4 < 32; k4++) {
                float w0 = sW1[(k4 * 4 + 0) * D + t];
                float w1 = sW1[(k4 * 4 + 1) * D + t];
                float w2 = sW1[(k4 * 4 + 2) * D + t];
                float w3 = sW1[(k4 * 4 + 3) * D + t];
                #pragma unroll
                for (int m = 0; m < 8; m++) {
                    float4 zv = sz[m * 32 + k4];
                    tv[m] = fmaf(w0, zv.x, tv[m]);
                    tv[m] = fmaf(w1, zv.y, tv[m]);
                    tv[m] = fmaf(w2, zv.z, tv[m]);
                    tv[m] = fmaf(w3, zv.w, tv[m]);
                }
            }
            float a = 0.f;
            #pragma unroll
            for (int m = 0; m < 8; m++)
                if (nb + m < n) a += fast_tanh(tv[m]);
            if (p) acc1 += a * w2v; else acc0 += a * w2v;
        }
    }
    __syncthreads();
    red[t] = acc0; __syncthreads();
    for (int d2 = 64; d2 > 0; d2 >>= 1) { if (t < d2) red[t] += red[t + d2]; __syncthreads(); }
    if (t == 0) atomicAdd(&S[0], red[0]);
    __syncthreads();
    red[t] = acc1; __syncthreads();
    for (int d2 = 64; d2 > 0; d2 >>= 1) { if (t < d2) red[t] += red[t + d2]; __syncthreads(); }
    if (t == 0) atomicAdd(&S[1], red[0]);
}

// ---------------- h = beta0*z0 + beta1*z1, beta = softmax of means ----------------
__global__ void k_combine(const float4* __restrict__ z0, const float4* __restrict__ z1,
                          const float* __restrict__ S, float invn, float4* __restrict__ h, int n4) {
    float m0 = S[0] * invn, m1 = S[1] * invn;
    float b0 = 1.0f / (1.0f + expf(m1 - m0));
    float b1 = 1.0f - b0;
    int i = blockIdx.x * blockDim.x + threadIdx.x, st = gridDim.x * blockDim.x;
    for (; i < n4; i += st) {
        float4 a = z0[i], b = z1[i];
        h[i] = make_float4(b0 * a.x + b1 * b.x, b0 * a.y + b1 * b.y,
                           b0 * a.z + b1 * b.z, b0 * a.w + b1 * b.w);
    }
}

// ---------------- SSL prep: e1=x[idx], e2=0.5h+0.5e1; store n1,n2,emb; accumulate 2*posdot ----------------
__global__ void k_sslprep(const int* __restrict__ idx, const float4* __restrict__ x, int xoff,
                          const float4* __restrict__ h, float4* __restrict__ n1,
                          float4* __restrict__ n2, float4* __restrict__ emb,
                          float* __restrict__ posAcc) {
    int b = (blockIdx.x * blockDim.x + threadIdx.x) >> 5;
    int lane = threadIdx.x & 31;
    if (b >= BSZ) return;
    int u = idx[b];
    float4 e1 = x[(xoff + u) * 32 + lane];
    float4 hv = h[u * 32 + lane];
    float4 e2 = make_float4(0.5f * (hv.x + e1.x), 0.5f * (hv.y + e1.y),
                            0.5f * (hv.z + e1.z), 0.5f * (hv.w + e1.w));
    float s11 = warp_sum(e1.x * e1.x + e1.y * e1.y + e1.z * e1.z + e1.w * e1.w);
    float s22 = warp_sum(e2.x * e2.x + e2.y * e2.y + e2.z * e2.z + e2.w * e2.w);
    float s12 = warp_sum(e1.x * e2.x + e1.y * e2.y + e1.z * e2.z + e1.w * e2.w);
    float inv1 = 1.0f / fmaxf(sqrtf(s11), 1e-12f);
    float inv2 = 1.0f / fmaxf(sqrtf(s22), 1e-12f);
    n1[b * 32 + lane] = make_float4(e1.x * inv1, e1.y * inv1, e1.z * inv1, e1.w * inv1);
    n2[b * 32 + lane] = make_float4(e2.x * inv2, e2.y * inv2, e2.z * inv2, e2.w * inv2);
    emb[b * 32 + lane] = e2;
    if (lane == 0) atomicAdd(posAcc, 2.0f * s12 * inv1 * inv2);
}

__global__ void k_gatherN(const int* __restrict__ idx, const float4* __restrict__ x, int xoff,
                          const float4* __restrict__ h, float4* __restrict__ emb) {
    int i = blockIdx.x * blockDim.x + threadIdx.x;
    if (i >= BSZ * 32) return;
    int b = i >> 5, lane = i & 31;
    int u = idx[b];
    float4 e1 = x[(xoff + u) * 32 + lane];
    float4 hv = h[u * 32 + lane];
    emb[i] = make_float4(0.5f * (hv.x + e1.x), 0.5f * (hv.y + e1.y),
                         0.5f * (hv.z + e1.z), 0.5f * (hv.w + e1.w));
}

// ---------------- alls[i] = sum_j exp(2 * n1_i . n2_j) ; 64x64 tiles ----------------
__global__ void k_alls(const float* __restrict__ n1, const float* __restrict__ n2,
                       float* __restrict__ alls) {
    __shared__ float sA[32][68];
    __shared__ float sB[32][68];
    int t = threadIdx.x;               // 256
    int tx = t & 15, ty = t >> 4;
    int i0 = blockIdx.y * 64, j0 = blockIdx.x * 64;
    float acc[4][4];
    #pragma unroll
    for (int a = 0; a < 4; a++)
        #pragma unroll
        for (int b = 0; b < 4; b++) acc[a][b] = 0.f;
    for (int kb = 0; kb < 128; kb += 32) {
        __syncthreads();
        for (int e = t; e < 2048; e += 256) {
            int r = e >> 5, k = e & 31;
            sA[k][r] = n1[(i0 + r) * 128 + kb + k];
            sB[k][r] = n2[(j0 + r) * 128 + kb + k];
        }
        __syncthreads();
        #pragma unroll 8
        for (int k = 0; k < 32; k++) {
            float4 a4 = *(const float4*)&sA[k][ty << 2];
            float4 b4 = *(const float4*)&sB[k][tx << 2];
            float av[4] = {a4.x, a4.y, a4.z, a4.w};
            float bv[4] = {b4.x, b4.y, b4.z, b4.w};
            #pragma unroll
            for (int a = 0; a < 4; a++)
                #pragma unroll
                for (int b = 0; b < 4; b++)
                    acc[a][b] = fmaf(av[a], bv[b], acc[a][b]);
        }
    }
    float rs[4] = {0.f, 0.f, 0.f, 0.f};
    #pragma unroll
    for (int a = 0; a < 4; a++)
        #pragma unroll
        for (int b = 0; b < 4; b++)
            rs[a] += __expf(2.0f * acc[a][b]);
    #pragma unroll
    for (int off = 8; off > 0; off >>= 1)
        #pragma unroll
        for (int a = 0; a < 4; a++)
            rs[a] += __shfl_down_sync(0xffffffffu, rs[a], off, 16);
    if (tx == 0)
        #pragma unroll
        for (int a = 0; a < 4; a++)
            atomicAdd(&alls[i0 + ty * 4 + a], rs[a]);
}

// ---------------- final per-row transform: out = LN(relu(E @ W + b)) ----------------
__global__ void k_transform(const float* __restrict__ E, const float* __restrict__ W,
                            const float* __restrict__ bias, const float* __restrict__ g,
                            const float* __restrict__ bb, float* __restrict__ out) {
    __shared__ float sz[8][128];
    __shared__ float ys[8][129];
    int t = threadIdx.x;              // 128 threads; t = out column
    int r0 = blockIdx.x * 8;
    for (int e = t; e < 8 * 128; e += 128) sz[e >> 7][e & 127] = E[r0 * 128 + e];
    __syncthreads();
    float acc[8];
    float bv = bias[t];
    #pragma unroll
    for (int m = 0; m < 8; m++) acc[m] = bv;
    #pragma unroll 4
    for (int k = 0; k < 128; k++) {
        float wv = W[k * 128 + t];
        #pragma unroll
        for (int m = 0; m < 8; m++) acc[m] = fmaf(sz[m][k], wv, acc[m]);
    }
    #pragma unroll
    for (int m = 0; m < 8; m++) ys[m][t] = fmaxf(acc[m], 0.f);
    __syncthreads();
    int wid = t >> 5, lane = t & 31;
    for (int r = wid; r < 8; r += 4) {
        float s = 0.f;
        for (int k = lane; k < 128; k += 32) s += ys[r][k];
        s = warp_sum(s);
        float mu = s * (1.0f / 128.0f);
        float vs = 0.f;
        for (int k = lane; k < 128; k += 32) { float d = ys[r][k] - mu; vs += d * d; }
        vs = warp_sum(vs);
        float rstd = rsqrtf(vs * (1.0f / 128.0f) + 1e-5f);
        for (int k = lane; k < 128; k += 32)
            out[(r0 + r) * 128 + k] = (ys[r][k] - mu) * rstd * g[k] + bb[k];
    }
}

// ---------------- final loss scalar ----------------
__global__ void k_loss(const float* __restrict__ alls, const float* __restrict__ pos,
                       float* __restrict__ out) {
    __shared__ float red[256];
    int t = threadIdx.x;
    float s = 0.f;
    for (int i = t; i < 2 * BSZ; i += 256) s += logf(alls[i]);
    red[t] = s; __syncthreads();
    for (int d2 = 128; d2 > 0; d2 >>= 1) { if (t < d2) red[t] += red[t + d2]; __syncthreads(); }
    if (t == 0) out[3 * BD] = (0.4f / (float)BSZ) * (red[0] - pos[0] - pos[2]);
}

// ---------------- launch ----------------
extern "C" void kernel_launch(void* const* d_in, const int* in_sizes, int n_in,
                              void* d_out, int out_size) {
    const float* feat_u  = (const float*)d_in[0];
    const float* feat_i  = (const float*)d_in[1];
    const float* uW1 = (const float*)d_in[2];
    const float* ub1 = (const float*)d_in[3];
    const float* uW2 = (const float*)d_in[4];
    const float* iW1 = (const float*)d_in[5];
    const float* ib1 = (const float*)d_in[6];
    const float* iW2 = (const float*)d_in[7];
    const float* userW = (const float*)d_in[8];
    const float* userB = (const float*)d_in[9];
    const float* itemW = (const float*)d_in[10];
    const float* itemB = (const float*)d_in[11];
    const float* lng = (const float*)d_in[12];
    const float* lnb = (const float*)d_in[13];
    const int* mpsrc[4] = {(const int*)d_in[14], (const int*)d_in[16],
                           (const int*)d_in[18], (const int*)d_in[20]};
    const int* mpdst[4] = {(const int*)d_in[15], (const int*)d_in[17],
                           (const int*)d_in[19], (const int*)d_in[21]};
    const int* ui_row = (const int*)d_in[22];
    const int* ui_col = (const int*)d_in[23];
    const int* user_idx = (const int*)d_in[24];
    const int* item_idx = (const int*)d_in[25];
    const int* neg_idx  = (const int*)d_in[26];
    float* out = (float*)d_out;

    // symbol addresses
    void *p_hu, *p_hi, *p_z0, *p_z1, *p_xA, *p_xB;
    void *p_mpcol, *p_mpoff, *p_mpcnt, *p_mpocnt, *p_mpcur, *p_oinv, *p_iinv;
    void *p_uicol, *p_uioff, *p_uicnt, *p_uicur, *p_dinv;
    void *p_S, *p_pos, *p_n1u, *p_n2u, *p_n1i, *p_n2i, *p_embU, *p_embI, *p_embN, *p_alls;
    cudaGetSymbolAddress(&p_hu, d_hu);     cudaGetSymbolAddress(&p_hi, d_hi);
    cudaGetSymbolAddress(&p_z0, d_z0);     cudaGetSymbolAddress(&p_z1, d_z1);
    cudaGetSymbolAddress(&p_xA, d_xA);     cudaGetSymbolAddress(&p_xB, d_xB);
    cudaGetSymbolAddress(&p_mpcol, d_mpcol);   cudaGetSymbolAddress(&p_mpoff, d_mpoff);
    cudaGetSymbolAddress(&p_mpcnt, d_mpcnt);   cudaGetSymbolAddress(&p_mpocnt, d_mpocnt);
    cudaGetSymbolAddress(&p_mpcur, d_mpcur);
    cudaGetSymbolAddress(&p_oinv, d_oinv);     cudaGetSymbolAddress(&p_iinv, d_iinv);
    cudaGetSymbolAddress(&p_uicol, d_uicol);   cudaGetSymbolAddress(&p_uioff, d_uioff);
    cudaGetSymbolAddress(&p_uicnt, d_uicnt);   cudaGetSymbolAddress(&p_uicur, d_uicur);
    cudaGetSymbolAddress(&p_dinv, d_dinv);
    cudaGetSymbolAddress(&p_S, d_S);           cudaGetSymbolAddress(&p_pos, d_pos);
    cudaGetSymbolAddress(&p_n1u, d_n1u);       cudaGetSymbolAddress(&p_n2u, d_n2u);
    cudaGetSymbolAddress(&p_n1i, d_n1i);       cudaGetSymbolAddress(&p_n2i, d_n2i);
    cudaGetSymbolAddress(&p_embU, d_embU);     cudaGetSymbolAddress(&p_embI, d_embI);
    cudaGetSymbolAddress(&p_embN, d_embN);     cudaGetSymbolAddress(&p_alls, d_alls);

    cudaFuncSetAttribute(k_att, cudaFuncAttributeMaxDynamicSharedMemorySize, 65536);

    float* hu = (float*)p_hu;   float* hi = (float*)p_hi;
    float* z0 = (float*)p_z0;   float* z1 = (float*)p_z1;
    float* xA = (float*)p_xA;   float* xB = (float*)p_xB;
    int* mpcol = (int*)p_mpcol; int* mpoff = (int*)p_mpoff;
    int* mpcnt = (int*)p_mpcnt; int* mpocnt = (int*)p_mpocnt; int* mpcur = (int*)p_mpcur;
    float* oinv = (float*)p_oinv; float* iinv = (float*)p_iinv;
    int* uicol = (int*)p_uicol; int* uioff = (int*)p_uioff;
    int* uicnt = (int*)p_uicnt; int* uicur = (int*)p_uicur;
    float* dinv = (float*)p_dinv;
    float* S = (float*)p_S;     float* pos = (float*)p_pos;
    float* n1u = (float*)p_n1u; float* n2u = (float*)p_n2u;
    float* n1i = (float*)p_n1i; float* n2i = (float*)p_n2i;
    float* embU = (float*)p_embU; float* embI = (float*)p_embI; float* embN = (float*)p_embN;
    float* alls = (float*)p_alls;

    // ---- zero per-call accumulators ----
    cudaMemsetAsync(p_mpcnt,  0, sizeof(int) * 4 * NU, 0);
    cudaMemsetAsync(p_mpocnt, 0, sizeof(int) * 4 * NU, 0);
    cudaMemsetAsync(p_mpcur,  0, sizeof(int) * 4 * NU, 0);
    cudaMemsetAsync(p_uicnt,  0, sizeof(int) * NT, 0);
    cudaMemsetAsync(p_uicur,  0, sizeof(int) * NT, 0);
    cudaMemsetAsync(p_S,    0, sizeof(float) * 12, 0);
    cudaMemsetAsync(p_pos,  0, sizeof(float) * 4, 0);
    cudaMemsetAsync(p_alls, 0, sizeof(float) * 2 * BSZ, 0);

    // ---- structure build ----
    for (int g = 0; g < 4; g++) {
        k_count<<<1024, 256>>>(mpdst[g], EMP, mpcnt + g * NU);
        k_count<<<1024, 256>>>(mpsrc[g], EMP, mpocnt + g * NU);
    }
    k_count<<<1024, 256>>>(ui_row, EUI, uicnt);
    for (int g = 0; g < 4; g++)
        k_scan<<<1, 1024>>>(mpcnt + g * NU, mpoff + g * (NU + 1), NU);
    k_scan<<<1, 1024>>>(uicnt, uioff, NT);
    k_inv_max1<<<160, 256>>>(mpocnt, oinv, 4 * NU);
    k_inv_max1<<<160, 256>>>(mpcnt, iinv, 4 * NU);
    k_inv_or0<<<160, 256>>>(uicnt, dinv, NT);
    for (int g = 0; g < 4; g++)
        k_fill<<<1024, 256>>>(mpdst[g], mpsrc[g], EMP, mpoff + g * (NU + 1),
                              mpcur + g * NU, mpcol + g * EMP);
    k_fill<<<1024, 256>>>(ui_row, ui_col, EUI, uioff, uicur, uicol);

    // ---- init h and x ----
    k_copy4<<<640, 256>>>((const float4*)feat_u, (float4*)hu, NU * 32);
    k_copy4<<<640, 256>>>((const float4*)feat_i, (float4*)hi, NI * 32);
    k_copy4<<<640, 256>>>((const float4*)feat_u, (float4*)xA, NU * 32);
    k_copy4<<<640, 256>>>((const float4*)feat_i, (float4*)(xA + NU * D), NI * 32);

    // ---- HAN: 3 iterations, user side (graphs 0,1) then item side (graphs 2,3) ----
    for (int side = 0; side < 2; side++) {
        float* h = side ? hi : hu;
        const float* W1 = side ? iW1 : uW1;
        const float* b1 = side ? ib1 : ub1;
        const float* W2 = side ? iW2 : uW2;
        int g0 = side * 2, g1 = side * 2 + 1;
        int n = side ? NI : NU;
        for (int it = 0; it < 3; it++) {
            k_conv<<<(n + 7) / 8, 256>>>((const float4*)h, mpoff + g0 * (NU + 1),
                mpcol + g0 * EMP, oinv + g0 * NU, iinv + g0 * NU, (float4*)z0, n);
            k_conv<<<(n + 7) / 8, 256>>>((const float4*)h, mpoff + g1 * (NU + 1),
                mpcol + g1 * EMP, oinv + g1 * NU, iinv + g1 * NU, (float4*)z1, n);
            float* Sp = S + 2 * (side * 3 + it);
            k_att<<<512, 128, 65536>>>(z0, z1, W1, b1, W2, Sp, n);
            k_combine<<<512, 256>>>((const float4*)z0, (const float4*)z1, Sp,
                                    1.0f / (float)n, (float4*)h, n * 32);
        }
    }

    // ---- LightGCN: 3 hops on UI graph (A -> B -> A -> B) ----
    k_conv<<<(NT + 7) / 8, 256>>>((const float4*)xA, uioff, uicol, dinv, dinv, (float4*)xB, NT);
    k_conv<<<(NT + 7) / 8, 256>>>((const float4*)xB, uioff, uicol, dinv, dinv, (float4*)xA, NT);
    k_conv<<<(NT + 7) / 8, 256>>>((const float4*)xA, uioff, uicol, dinv, dinv, (float4*)xB, NT);

    // ---- SSL prep + gathers ----
    k_sslprep<<<1024, 256>>>(user_idx, (const float4*)xB, 0, (const float4*)hu,
                             (float4*)n1u, (float4*)n2u, (float4*)embU, pos + 0);
    k_sslprep<<<1024, 256>>>(item_idx, (const float4*)xB, NU, (const float4*)hi,
                             (float4*)n1i, (float4*)n2i, (float4*)embI, pos + 2);
    k_gatherN<<<1024, 256>>>(neg_idx, (const float4*)xB, NU, (const float4*)hi, (float4*)embN);

    // ---- SSL alls (the big one) ----
    dim3 ag(128, 128);
    k_alls<<<ag, 256>>>(n1u, n2u, alls);
    k_alls<<<ag, 256>>>(n1i, n2i, alls + BSZ);

    // ---- final transforms (only gathered rows) ----
    k_transform<<<BSZ / 8, 128>>>(embU, userW, userB, lng, lnb, out);
    k_transform<<<BSZ / 8, 128>>>(embI, itemW, itemB, lng, lnb, out + BD);
    k_transform<<<BSZ / 8, 128>>>(embN, itemW, itemB, lng, lnb, out + 2 * BD);

    // ---- loss scalar ----
    k_loss<<<1, 256>>>(alls, pos, out);
}

// round 7
// speedup vs baseline: 1.4694x; 1.4694x over previous
#include <cuda_runtime.h>
#include <cuda_bf16.h>
#include <cstdint>
#include <cstddef>
#include <math.h>

// ---------------- problem constants ----------------
constexpr int NU  = 40000;
constexpr int NI  = 40000;
constexpr int NT  = 80000;      // NU + NI
constexpr int D   = 128;
constexpr int EMP = 640000;
constexpr int EUI = 1600000;
constexpr int BSZ = 8192;
constexpr int BD  = BSZ * D;

// ---------------- device scratch (no allocs allowed) ----------------
__device__ float d_hu[NU * D];
__device__ float d_hi[NI * D];
__device__ float d_z0[NU * D];
__device__ float d_z1[NU * D];
__device__ float d_xA[NT * D];
__device__ float d_xB[NT * D];

__device__ int   d_mpcol[4 * EMP];
__device__ int   d_mpoff[4 * (NU + 1)];
__device__ int   d_mpcnt[4 * NU];     // dst counts
__device__ int   d_mpocnt[4 * NU];    // src counts
__device__ int   d_mpcur[4 * NU];
__device__ float d_oinv[4 * NU];
__device__ float d_iinv[4 * NU];

__device__ int   d_uicol[EUI];
__device__ int   d_uioff[NT + 1];
__device__ int   d_uicnt[NT];
__device__ int   d_uicur[NT];
__device__ float d_dinv[NT];

__device__ float d_S[12];     // attention score sums (2 per side-iter)
__device__ float d_pos[4];    // [0]=2*posdot sum U, [2]=2*posdot sum I
__device__ __nv_bfloat16 d_b1u[BD];
__device__ __nv_bfloat16 d_b2u[BD];
__device__ __nv_bfloat16 d_b1i[BD];
__device__ __nv_bfloat16 d_b2i[BD];
__device__ float d_embU[BD];
__device__ float d_embI[BD];
__device__ float d_embN[BD];
__device__ float d_alls[2 * BSZ];
__device__ int   d_work;

// ---------------- helpers ----------------
__device__ __forceinline__ float warp_sum(float v) {
    #pragma unroll
    for (int d2 = 16; d2 > 0; d2 >>= 1) v += __shfl_down_sync(0xffffffffu, v, d2);
    return __shfl_sync(0xffffffffu, v, 0);
}
__device__ __forceinline__ float fast_tanh(float x) {
    float y; asm("tanh.approx.f32 %0, %1;" : "=f"(y) : "f"(x)); return y;
}
__device__ __forceinline__ void ldsm_x4(uint32_t& r0, uint32_t& r1, uint32_t& r2, uint32_t& r3,
                                        uint32_t addr) {
    asm volatile("ldmatrix.sync.aligned.m8n8.x4.shared.b16 {%0,%1,%2,%3}, [%4];"
        : "=r"(r0), "=r"(r1), "=r"(r2), "=r"(r3) : "r"(addr));
}
__device__ __forceinline__ void mma16816(float* c, const uint32_t* a, const uint32_t* b) {
    asm volatile("mma.sync.aligned.m16n8k16.row.col.f32.bf16.bf16.f32 "
        "{%0,%1,%2,%3},{%4,%5,%6,%7},{%8,%9},{%0,%1,%2,%3};"
        : "+f"(c[0]), "+f"(c[1]), "+f"(c[2]), "+f"(c[3])
        : "r"(a[0]), "r"(a[1]), "r"(a[2]), "r"(a[3]), "r"(b[0]), "r"(b[1]));
}

// ---------------- structure kernels ----------------
__global__ void k_count(const int* __restrict__ a, int n, int* __restrict__ cnt) {
    int i = blockIdx.x * blockDim.x + threadIdx.x, st = gridDim.x * blockDim.x;
    for (; i < n; i += st) atomicAdd(&cnt[a[i]], 1);
}
__global__ void k_inv_max1(const int* __restrict__ cnt, float* __restrict__ inv, int n) {
    int i = blockIdx.x * blockDim.x + threadIdx.x, st = gridDim.x * blockDim.x;
    for (; i < n; i += st) { int c = cnt[i]; inv[i] = rsqrtf((float)(c > 1 ? c : 1)); }
}
__global__ void k_inv_or0(const int* __restrict__ cnt, float* __restrict__ inv, int n) {
    int i = blockIdx.x * blockDim.x + threadIdx.x, st = gridDim.x * blockDim.x;
    for (; i < n; i += st) { int c = cnt[i]; inv[i] = (c > 0) ? rsqrtf((float)c) : 0.0f; }
}

// single-block chunked exclusive scan: off[0..n]; 1024 threads, 4 elems/thread/chunk
__global__ void k_scan(const int* __restrict__ cnt, int* __restrict__ off, int n) {
    __shared__ int wsum[32];
    __shared__ int carry_s;
    int t = threadIdx.x, lane = t & 31, wid = t >> 5;
    if (t == 0) { carry_s = 0; off[0] = 0; }
    __syncthreads();
    for (int base = 0; base < n; base += 4096) {
        int idx0 = base + t * 4;
        int v0 = (idx0 + 0 < n) ? cnt[idx0 + 0] : 0;
        int v1 = (idx0 + 1 < n) ? cnt[idx0 + 1] : 0;
        int v2 = (idx0 + 2 < n) ? cnt[idx0 + 2] : 0;
        int v3 = (idx0 + 3 < n) ? cnt[idx0 + 3] : 0;
        v1 += v0; v2 += v1; v3 += v2;
        int ts = v3, sc = ts;
        #pragma unroll
        for (int d2 = 1; d2 < 32; d2 <<= 1) {
            int x = __shfl_up_sync(0xffffffffu, sc, d2);
            if (lane >= d2) sc += x;
        }
        if (lane == 31) wsum[wid] = sc;
        __syncthreads();
        if (wid == 0) {
            int s2 = wsum[lane];
            #pragma unroll
            for (int d2 = 1; d2 < 32; d2 <<= 1) {
                int x = __shfl_up_sync(0xffffffffu, s2, d2);
                if (lane >= d2) s2 += x;
            }
            wsum[lane] = s2;
        }
        __syncthreads();
        int woff = wid ? wsum[wid - 1] : 0;
        int b0 = carry_s + woff + (sc - ts);
        if (idx0 + 0 < n) off[idx0 + 1] = b0 + v0;
        if (idx0 + 1 < n) off[idx0 + 2] = b0 + v1;
        if (idx0 + 2 < n) off[idx0 + 3] = b0 + v2;
        if (idx0 + 3 < n) off[idx0 + 4] = b0 + v3;
        __syncthreads();
        if (t == 0) carry_s += wsum[31];
        __syncthreads();
    }
}

__global__ void k_fill(const int* __restrict__ key, const int* __restrict__ val, int n,
                       const int* __restrict__ off, int* __restrict__ cur, int* __restrict__ col) {
    int i = blockIdx.x * blockDim.x + threadIdx.x, st = gridDim.x * blockDim.x;
    for (; i < n; i += st) {
        int k = key[i];
        col[off[k] + atomicAdd(&cur[k], 1)] = val[i];
    }
}

__global__ void k_copy4(const float4* __restrict__ s, float4* __restrict__ d, int n) {
    int i = blockIdx.x * blockDim.x + threadIdx.x, st = gridDim.x * blockDim.x;
    for (; i < n; i += st) d[i] = s[i];
}

// ---------------- normalized graph conv: z[w] = dinv[w]*sum_{c in adj(w)} sinv[c]*h[c] ----------------
__global__ void k_conv(const float4* __restrict__ h, const int* __restrict__ off,
                       const int* __restrict__ col, const float* __restrict__ sinv,
                       const float* __restrict__ dinv, float4* __restrict__ z, int n) {
    int w = (blockIdx.x * blockDim.x + threadIdx.x) >> 5;
    int lane = threadIdx.x & 31;
    if (w >= n) return;
    int s = off[w], e = off[w + 1];
    float ax = 0.f, ay = 0.f, az = 0.f, aw = 0.f;
    for (int k = s; k < e; k++) {
        int c = col[k];
        float wt = sinv[c];
        float4 v = h[c * 32 + lane];
        ax = fmaf(wt, v.x, ax); ay = fmaf(wt, v.y, ay);
        az = fmaf(wt, v.z, az); aw = fmaf(wt, v.w, aw);
    }
    float di = dinv[w];
    z[w * 32 + lane] = make_float4(ax * di, ay * di, az * di, aw * di);
}

// ---------------- semantic attention scores: S[p] += sum_n tanh(z_p[n]@W1+b1)@W2 ----------------
__global__ void k_att(const float* __restrict__ z0, const float* __restrict__ z1,
                      const float* __restrict__ W1, const float* __restrict__ b1,
                      const float* __restrict__ W2, float* __restrict__ S, int n) {
    extern __shared__ float sW1[];        // 128*128 floats, natural layout
    __shared__ float4 sz[8 * 32];
    __shared__ float red[128];
    int t = threadIdx.x;                  // 128 threads; t = hidden column j
    for (int i = t; i < D * D; i += 128) sW1[i] = W1[i];
    float bv = b1[t], w2v = W2[t];
    __syncthreads();
    float acc0 = 0.f, acc1 = 0.f;
    for (int nb = blockIdx.x * 8; nb < n; nb += gridDim.x * 8) {
        #pragma unroll
        for (int p = 0; p < 2; p++) {
            const float4* z4 = (const float4*)(p ? z1 : z0);
            __syncthreads();
            for (int q = t; q < 256; q += 128) {
                int row = nb + (q >> 5);
                sz[q] = (row < n) ? z4[row * 32 + (q & 31)] : make_float4(0.f, 0.f, 0.f, 0.f);
            }
            __syncthreads();
            float tv[8];
            #pragma unroll
            for (int m = 0; m < 8; m++) tv[m] = bv;
            #pragma unroll 4
            for (int k4 = 0; k4 < 32; k4++) {
                float w0 = sW1[(k4 * 4 + 0) * D + t];
                float w1 = sW1[(k4 * 4 + 1) * D + t];
                float w2 = sW1[(k4 * 4 + 2) * D + t];
                float w3 = sW1[(k4 * 4 + 3) * D + t];
                #pragma unroll
                for (int m = 0; m < 8; m++) {
                    float4 zv = sz[m * 32 + k4];
                    tv[m] = fmaf(w0, zv.x, tv[m]);
                    tv[m] = fmaf(w1, zv.y, tv[m]);
                    tv[m] = fmaf(w2, zv.z, tv[m]);
                    tv[m] = fmaf(w3, zv.w, tv[m]);
                }
            }
            float a = 0.f;
            #pragma unroll
            for (int m = 0; m < 8; m++)
                if (nb + m < n) a += fast_tanh(tv[m]);
            if (p) acc1 += a * w2v; else acc0 += a * w2v;
        }
    }
    __syncthreads();
    red[t] = acc0; __syncthreads();
    for (int d2 = 64; d2 > 0; d2 >>= 1) { if (t < d2) red[t] += red[t + d2]; __syncthreads(); }
    if (t == 0) atomicAdd(&S[0], red[0]);
    __syncthreads();
    red[t] = acc1; __syncthreads();
    for (int d2 = 64; d2 > 0; d2 >>= 1) { if (t < d2) red[t] += red[t + d2]; __syncthreads(); }
    if (t == 0) atomicAdd(&S[1], red[0]);
}

// ---------------- h = beta0*z0 + beta1*z1, beta = softmax of means ----------------
__global__ void k_combine(const float4* __restrict__ z0, const float4* __restrict__ z1,
                          const float* __restrict__ S, float invn, float4* __restrict__ h, int n4) {
    float m0 = S[0] * invn, m1 = S[1] * invn;
    float b0 = 1.0f / (1.0f + expf(m1 - m0));
    float b1 = 1.0f - b0;
    int i = blockIdx.x * blockDim.x + threadIdx.x, st = gridDim.x * blockDim.x;
    for (; i < n4; i += st) {
        float4 a = z0[i], b = z1[i];
        h[i] = make_float4(b0 * a.x + b1 * b.x, b0 * a.y + b1 * b.y,
                           b0 * a.z + b1 * b.z, b0 * a.w + b1 * b.w);
    }
}

// ---------------- SSL prep: e1=x[idx], e2=0.5h+0.5e1; bf16 n1,n2; emb; 2*posdot ----------------
__global__ void k_sslprep(const int* __restrict__ idx, const float4* __restrict__ x, int xoff,
                          const float4* __restrict__ h, __nv_bfloat16* __restrict__ n1b,
                          __nv_bfloat16* __restrict__ n2b, float4* __restrict__ emb,
                          float* __restrict__ posAcc) {
    int b = (blockIdx.x * blockDim.x + threadIdx.x) >> 5;
    int lane = threadIdx.x & 31;
    if (b >= BSZ) return;
    int u = idx[b];
    float4 e1 = x[(xoff + u) * 32 + lane];
    float4 hv = h[u * 32 + lane];
    float4 e2 = make_float4(0.5f * (hv.x + e1.x), 0.5f * (hv.y + e1.y),
                            0.5f * (hv.z + e1.z), 0.5f * (hv.w + e1.w));
    float s11 = warp_sum(e1.x * e1.x + e1.y * e1.y + e1.z * e1.z + e1.w * e1.w);
    float s22 = warp_sum(e2.x * e2.x + e2.y * e2.y + e2.z * e2.z + e2.w * e2.w);
    float s12 = warp_sum(e1.x * e2.x + e1.y * e2.y + e1.z * e2.z + e1.w * e2.w);
    float inv1 = 1.0f / fmaxf(sqrtf(s11), 1e-12f);
    float inv2 = 1.0f / fmaxf(sqrtf(s22), 1e-12f);
    __nv_bfloat162* p1 = (__nv_bfloat162*)&n1b[b * 128 + lane * 4];
    p1[0] = __float22bfloat162_rn(make_float2(e1.x * inv1, e1.y * inv1));
    p1[1] = __float22bfloat162_rn(make_float2(e1.z * inv1, e1.w * inv1));
    __nv_bfloat162* p2 = (__nv_bfloat162*)&n2b[b * 128 + lane * 4];
    p2[0] = __float22bfloat162_rn(make_float2(e2.x * inv2, e2.y * inv2));
    p2[1] = __float22bfloat162_rn(make_float2(e2.z * inv2, e2.w * inv2));
    emb[b * 32 + lane] = e2;
    if (lane == 0) atomicAdd(posAcc, 2.0f * s12 * inv1 * inv2);
}

__global__ void k_gatherN(const int* __restrict__ idx, const float4* __restrict__ x, int xoff,
                          const float4* __restrict__ h, float4* __restrict__ emb) {
    int i = blockIdx.x * blockDim.x + threadIdx.x;
    if (i >= BSZ * 32) return;
    int b = i >> 5, lane = i & 31;
    int u = idx[b];
    float4 e1 = x[(xoff + u) * 32 + lane];
    float4 hv = h[u * 32 + lane];
    emb[i] = make_float4(0.5f * (hv.x + e1.x), 0.5f * (hv.y + e1.y),
                         0.5f * (hv.z + e1.z), 0.5f * (hv.w + e1.w));
}

// ---------------- alls[i] = sum_j exp(2 * n1_i . n2_j), tensor-core version ----------------
// Persistent grid; work units = (side, 128-row block, 1024-col slice) -> 2*64*8 = 1024 units.
// Block tile 128 x 64, K = 128 resident. 8 warps as 4(m) x 2(n); warp tile 32 x 32.
// smem rows padded to 272B for conflict-free ldmatrix.
__global__ void __launch_bounds__(256, 2)
k_alls_mma(const __nv_bfloat16* __restrict__ n1u, const __nv_bfloat16* __restrict__ n2u,
           const __nv_bfloat16* __restrict__ n1i, const __nv_bfloat16* __restrict__ n2i,
           float* __restrict__ alls, int* __restrict__ work) {
    extern __shared__ char sm[];
    char* smA  = sm;             // 128 * 272 = 34816
    char* smB0 = sm + 34816;     // 64 * 272  = 17408
    char* smB1 = sm + 52224;
    __shared__ int s_unit;
    int tid = threadIdx.x;
    int lane = tid & 31, warp = tid >> 5;
    int warpM = warp >> 1, warpN = warp & 1;
    uint32_t smA_u  = (uint32_t)__cvta_generic_to_shared(smA);
    uint32_t smB0_u = (uint32_t)__cvta_generic_to_shared(smB0);
    uint32_t smB1_u = (uint32_t)__cvta_generic_to_shared(smB1);
    while (true) {
        __syncthreads();            // previous unit's compute done before smem reuse
        if (tid == 0) s_unit = atomicAdd(work, 1);
        __syncthreads();
        int u = s_unit;
        if (u >= 1024) return;
        int side = u >> 9;
        int rem = u & 511;
        int ib = rem >> 3, js = rem & 7;
        const __nv_bfloat16* A = side ? n1i : n1u;
        const __nv_bfloat16* B = side ? n2i : n2u;
        float* allsP = alls + side * BSZ;
        int i0 = ib * 128;
        // load A tile (once per unit)
        #pragma unroll
        for (int i = 0; i < 8; i++) {
            int e = tid + 256 * i;
            int r = e >> 4, c = e & 15;
            uint4 v = *(const uint4*)((const char*)A + (i0 + r) * 256 + c * 16);
            *(uint4*)(smA + r * 272 + c * 16) = v;
        }
        float rs0 = 0.f, rs1 = 0.f, rs2 = 0.f, rs3 = 0.f;
        int j0 = js * 1024;
        uint4 pb[4];
        #pragma unroll
        for (int i = 0; i < 4; i++) {
            int e = tid + 256 * i;
            int r = e >> 4, c = e & 15;
            pb[i] = *(const uint4*)((const char*)B + (j0 + r) * 256 + c * 16);
        }
        for (int jt = 0; jt < 16; jt++) {
            int cur = jt & 1;
            char* sBw = cur ? smB1 : smB0;
            uint32_t sB = cur ? smB1_u : smB0_u;
            __syncthreads();
            #pragma unroll
            for (int i = 0; i < 4; i++) {
                int e = tid + 256 * i;
                int r = e >> 4, c = e & 15;
                *(uint4*)(sBw + r * 272 + c * 16) = pb[i];
            }
            if (jt < 15) {
                int jn = j0 + (jt + 1) * 64;
                #pragma unroll
                for (int i = 0; i < 4; i++) {
                    int e = tid + 256 * i;
                    int r = e >> 4, c = e & 15;
                    pb[i] = *(const uint4*)((const char*)B + (jn + r) * 256 + c * 16);
                }
            }
            __syncthreads();
            float c_[2][4][4];
            #pragma unroll
            for (int mt = 0; mt < 2; mt++)
                #pragma unroll
                for (int nt = 0; nt < 4; nt++)
                    #pragma unroll
                    for (int e2 = 0; e2 < 4; e2++) c_[mt][nt][e2] = 0.f;
            int q = lane >> 3, l7 = lane & 7;
            #pragma unroll
            for (int ks = 0; ks < 8; ks++) {
                uint32_t af[2][4];
                uint32_t bfr[2][4];
                #pragma unroll
                for (int mt = 0; mt < 2; mt++) {
                    int row = warpM * 32 + mt * 16 + (q & 1) * 8 + l7;
                    int kc = ks * 16 + (q >> 1) * 8;
                    ldsm_x4(af[mt][0], af[mt][1], af[mt][2], af[mt][3],
                            smA_u + row * 272 + kc * 2);
                }
                #pragma unroll
                for (int p = 0; p < 2; p++) {
                    int colv = warpN * 32 + p * 16 + (q >> 1) * 8 + l7;
                    int kc = ks * 16 + (q & 1) * 8;
                    ldsm_x4(bfr[p][0], bfr[p][1], bfr[p][2], bfr[p][3],
                            sB + colv * 272 + kc * 2);
                }
                #pragma unroll
                for (int mt = 0; mt < 2; mt++) {
                    mma16816(c_[mt][0], af[mt], &bfr[0][0]);
                    mma16816(c_[mt][1], af[mt], &bfr[0][2]);
                    mma16816(c_[mt][2], af[mt], &bfr[1][0]);
                    mma16816(c_[mt][3], af[mt], &bfr[1][2]);
                }
            }
            #pragma unroll
            for (int nt = 0; nt < 4; nt++) {
                rs0 += __expf(2.f * c_[0][nt][0]) + __expf(2.f * c_[0][nt][1]);
                rs1 += __expf(2.f * c_[0][nt][2]) + __expf(2.f * c_[0][nt][3]);
                rs2 += __expf(2.f * c_[1][nt][0]) + __expf(2.f * c_[1][nt][1]);
                rs3 += __expf(2.f * c_[1][nt][2]) + __expf(2.f * c_[1][nt][3]);
            }
        }
        // reduce over the quad (columns live on lanes differing in lane%4)
        #pragma unroll
        for (int d2 = 1; d2 <= 2; d2 <<= 1) {
            rs0 += __shfl_xor_sync(0xffffffffu, rs0, d2);
            rs1 += __shfl_xor_sync(0xffffffffu, rs1, d2);
            rs2 += __shfl_xor_sync(0xffffffffu, rs2, d2);
            rs3 += __shfl_xor_sync(0xffffffffu, rs3, d2);
        }
        if ((lane & 3) == 0) {
            int g = lane >> 2;
            int rb = i0 + warpM * 32;
            atomicAdd(&allsP[rb + g],      rs0);
            atomicAdd(&allsP[rb + 8 + g],  rs1);
            atomicAdd(&allsP[rb + 16 + g], rs2);
            atomicAdd(&allsP[rb + 24 + g], rs3);
        }
    }
}

// ---------------- final per-row transform: out = LN(relu(E @ W + b)) ----------------
__global__ void k_transform(const float* __restrict__ E, const float* __restrict__ W,
                            const float* __restrict__ bias, const float* __restrict__ g,
                            const float* __restrict__ bb, float* __restrict__ out) {
    __shared__ float sz[8][128];
    __shared__ float ys[8][129];
    int t = threadIdx.x;              // 128 threads; t = out column
    int r0 = blockIdx.x * 8;
    for (int e = t; e < 8 * 128; e += 128) sz[e >> 7][e & 127] = E[r0 * 128 + e];
    __syncthreads();
    float acc[8];
    float bv = bias[t];
    #pragma unroll
    for (int m = 0; m < 8; m++) acc[m] = bv;
    #pragma unroll 4
    for (int k = 0; k < 128; k++) {
        float wv = W[k * 128 + t];
        #pragma unroll
        for (int m = 0; m < 8; m++) acc[m] = fmaf(sz[m][k], wv, acc[m]);
    }
    #pragma unroll
    for (int m = 0; m < 8; m++) ys[m][t] = fmaxf(acc[m], 0.f);
    __syncthreads();
    int wid = t >> 5, lane = t & 31;
    for (int r = wid; r < 8; r += 4) {
        float s = 0.f;
        for (int k = lane; k < 128; k += 32) s += ys[r][k];
        s = warp_sum(s);
        float mu = s * (1.0f / 128.0f);
        float vs = 0.f;
        for (int k = lane; k < 128; k += 32) { float d = ys[r][k] - mu; vs += d * d; }
        vs = warp_sum(vs);
        float rstd = rsqrtf(vs * (1.0f / 128.0f) + 1e-5f);
        for (int k = lane; k < 128; k += 32)
            out[(r0 + r) * 128 + k] = (ys[r][k] - mu) * rstd * g[k] + bb[k];
    }
}

// ---------------- final loss scalar ----------------
__global__ void k_loss(const float* __restrict__ alls, const float* __restrict__ pos,
                       float* __restrict__ out) {
    __shared__ float red[256];
    int t = threadIdx.x;
    float s = 0.f;
    for (int i = t; i < 2 * BSZ; i += 256) s += logf(alls[i]);
    red[t] = s; __syncthreads();
    for (int d2 = 128; d2 > 0; d2 >>= 1) { if (t < d2) red[t] += red[t + d2]; __syncthreads(); }
    if (t == 0) out[3 * BD] = (0.4f / (float)BSZ) * (red[0] - pos[0] - pos[2]);
}

// ---------------- launch ----------------
extern "C" void kernel_launch(void* const* d_in, const int* in_sizes, int n_in,
                              void* d_out, int out_size) {
    const float* feat_u  = (const float*)d_in[0];
    const float* feat_i  = (const float*)d_in[1];
    const float* uW1 = (const float*)d_in[2];
    const float* ub1 = (const float*)d_in[3];
    const float* uW2 = (const float*)d_in[4];
    const float* iW1 = (const float*)d_in[5];
    const float* ib1 = (const float*)d_in[6];
    const float* iW2 = (const float*)d_in[7];
    const float* userW = (const float*)d_in[8];
    const float* userB = (const float*)d_in[9];
    const float* itemW = (const float*)d_in[10];
    const float* itemB = (const float*)d_in[11];
    const float* lng = (const float*)d_in[12];
    const float* lnb = (const float*)d_in[13];
    const int* mpsrc[4] = {(const int*)d_in[14], (const int*)d_in[16],
                           (const int*)d_in[18], (const int*)d_in[20]};
    const int* mpdst[4] = {(const int*)d_in[15], (const int*)d_in[17],
                           (const int*)d_in[19], (const int*)d_in[21]};
    const int* ui_row = (const int*)d_in[22];
    const int* ui_col = (const int*)d_in[23];
    const int* user_idx = (const int*)d_in[24];
    const int* item_idx = (const int*)d_in[25];
    const int* neg_idx  = (const int*)d_in[26];
    float* out = (float*)d_out;

    void* p_hu = 0;    void* p_hi = 0;    void* p_z0 = 0;    void* p_z1 = 0;
    void* p_xA = 0;    void* p_xB = 0;
    void* p_mpcol = 0; void* p_mpoff = 0; void* p_mpcnt = 0; void* p_mpocnt = 0;
    void* p_mpcur = 0; void* p_oinv = 0;  void* p_iinv = 0;
    void* p_uicol = 0; void* p_uioff = 0; void* p_uicnt = 0; void* p_uicur = 0;
    void* p_dinv = 0;
    void* p_S = 0;     void* p_pos = 0;
    void* p_b1u = 0;   void* p_b2u = 0;   void* p_b1i = 0;   void* p_b2i = 0;
    void* p_embU = 0;  void* p_embI = 0;  void* p_embN = 0;
    void* p_alls = 0;  void* p_work = 0;
    cudaGetSymbolAddress(&p_hu, d_hu);
    cudaGetSymbolAddress(&p_hi, d_hi);
    cudaGetSymbolAddress(&p_z0, d_z0);
    cudaGetSymbolAddress(&p_z1, d_z1);
    cudaGetSymbolAddress(&p_xA, d_xA);
    cudaGetSymbolAddress(&p_xB, d_xB);
    cudaGetSymbolAddress(&p_mpcol, d_mpcol);
    cudaGetSymbolAddress(&p_mpoff, d_mpoff);
    cudaGetSymbolAddress(&p_mpcnt, d_mpcnt);
    cudaGetSymbolAddress(&p_mpocnt, d_mpocnt);
    cudaGetSymbolAddress(&p_mpcur, d_mpcur);
    cudaGetSymbolAddress(&p_oinv, d_oinv);
    cudaGetSymbolAddress(&p_iinv, d_iinv);
    cudaGetSymbolAddress(&p_uicol, d_uicol);
    cudaGetSymbolAddress(&p_uioff, d_uioff);
    cudaGetSymbolAddress(&p_uicnt, d_uicnt);
    cudaGetSymbolAddress(&p_uicur, d_uicur);
    cudaGetSymbolAddress(&p_dinv, d_dinv);
    cudaGetSymbolAddress(&p_S, d_S);
    cudaGetSymbolAddress(&p_pos, d_pos);
    cudaGetSymbolAddress(&p_b1u, d_b1u);
    cudaGetSymbolAddress(&p_b2u, d_b2u);
    cudaGetSymbolAddress(&p_b1i, d_b1i);
    cudaGetSymbolAddress(&p_b2i, d_b2i);
    cudaGetSymbolAddress(&p_embU, d_embU);
    cudaGetSymbolAddress(&p_embI, d_embI);
    cudaGetSymbolAddress(&p_embN, d_embN);
    cudaGetSymbolAddress(&p_alls, d_alls);
    cudaGetSymbolAddress(&p_work, d_work);

    cudaFuncSetAttribute(k_att, cudaFuncAttributeMaxDynamicSharedMemorySize, 65536);
    cudaFuncSetAttribute(k_alls_mma, cudaFuncAttributeMaxDynamicSharedMemorySize, 69632);

    float* hu = (float*)p_hu;
    float* hi = (float*)p_hi;
    float* z0 = (float*)p_z0;
    float* z1 = (float*)p_z1;
    float* xA = (float*)p_xA;
    float* xB = (float*)p_xB;
    int* mpcol = (int*)p_mpcol;
    int* mpoff = (int*)p_mpoff;
    int* mpcnt = (int*)p_mpcnt;
    int* mpocnt = (int*)p_mpocnt;
    int* mpcur = (int*)p_mpcur;
    float* oinv = (float*)p_oinv;
    float* iinv = (float*)p_iinv;
    int* uicol = (int*)p_uicol;
    int* uioff = (int*)p_uioff;
    int* uicnt = (int*)p_uicnt;
    int* uicur = (int*)p_uicur;
    float* dinv = (float*)p_dinv;
    float* S = (float*)p_S;
    float* pos = (float*)p_pos;
    __nv_bfloat16* b1u = (__nv_bfloat16*)p_b1u;
    __nv_bfloat16* b2u = (__nv_bfloat16*)p_b2u;
    __nv_bfloat16* b1i = (__nv_bfloat16*)p_b1i;
    __nv_bfloat16* b2i = (__nv_bfloat16*)p_b2i;
    float* embU = (float*)p_embU;
    float* embI = (float*)p_embI;
    float* embN = (float*)p_embN;
    float* alls = (float*)p_alls;
    int* work = (int*)p_work;

    // ---- zero per-call accumulators ----
    cudaMemsetAsync(p_mpcnt,  0, sizeof(int) * 4 * NU, 0);
    cudaMemsetAsync(p_mpocnt, 0, sizeof(int) * 4 * NU, 0);
    cudaMemsetAsync(p_mpcur,  0, sizeof(int) * 4 * NU, 0);
    cudaMemsetAsync(p_uicnt,  0, sizeof(int) * NT, 0);
    cudaMemsetAsync(p_uicur,  0, sizeof(int) * NT, 0);
    cudaMemsetAsync(p_S,    0, sizeof(float) * 12, 0);
    cudaMemsetAsync(p_pos,  0, sizeof(float) * 4, 0);
    cudaMemsetAsync(p_alls, 0, sizeof(float) * 2 * BSZ, 0);
    cudaMemsetAsync(p_work, 0, sizeof(int), 0);

    // ---- structure build ----
    for (int g = 0; g < 4; g++) {
        k_count<<<1024, 256>>>(mpdst[g], EMP, mpcnt + g * NU);
        k_count<<<1024, 256>>>(mpsrc[g], EMP, mpocnt + g * NU);
    }
    k_count<<<1024, 256>>>(ui_row, EUI, uicnt);
    for (int g = 0; g < 4; g++)
        k_scan<<<1, 1024>>>(mpcnt + g * NU, mpoff + g * (NU + 1), NU);
    k_scan<<<1, 1024>>>(uicnt, uioff, NT);
    k_inv_max1<<<160, 256>>>(mpocnt, oinv, 4 * NU);
    k_inv_max1<<<160, 256>>>(mpcnt, iinv, 4 * NU);
    k_inv_or0<<<160, 256>>>(uicnt, dinv, NT);
    for (int g = 0; g < 4; g++)
        k_fill<<<1024, 256>>>(mpdst[g], mpsrc[g], EMP, mpoff + g * (NU + 1),
                              mpcur + g * NU, mpcol + g * EMP);
    k_fill<<<1024, 256>>>(ui_row, ui_col, EUI, uioff, uicur, uicol);

    // ---- init h and x ----
    k_copy4<<<640, 256>>>((const float4*)feat_u, (float4*)hu, NU * 32);
    k_copy4<<<640, 256>>>((const float4*)feat_i, (float4*)hi, NI * 32);
    k_copy4<<<640, 256>>>((const float4*)feat_u, (float4*)xA, NU * 32);
    k_copy4<<<640, 256>>>((const float4*)feat_i, (float4*)(xA + NU * D), NI * 32);

    // ---- HAN: 3 iterations per side ----
    for (int side = 0; side < 2; side++) {
        float* h = side ? hi : hu;
        const float* W1 = side ? iW1 : uW1;
        const float* b1 = side ? ib1 : ub1;
        const float* W2 = side ? iW2 : uW2;
        int g0 = side * 2, g1 = side * 2 + 1;
        int n = side ? NI : NU;
        for (int it = 0; it < 3; it++) {
            k_conv<<<(n + 7) / 8, 256>>>((const float4*)h, mpoff + g0 * (NU + 1),
                mpcol + g0 * EMP, oinv + g0 * NU, iinv + g0 * NU, (float4*)z0, n);
            k_conv<<<(n + 7) / 8, 256>>>((const float4*)h, mpoff + g1 * (NU + 1),
                mpcol + g1 * EMP, oinv + g1 * NU, iinv + g1 * NU, (float4*)z1, n);
            float* Sp = S + 2 * (side * 3 + it);
            k_att<<<512, 128, 65536>>>(z0, z1, W1, b1, W2, Sp, n);
            k_combine<<<512, 256>>>((const float4*)z0, (const float4*)z1, Sp,
                                    1.0f / (float)n, (float4*)h, n * 32);
        }
    }

    // ---- LightGCN: 3 hops on UI graph ----
    k_conv<<<(NT + 7) / 8, 256>>>((const float4*)xA, uioff, uicol, dinv, dinv, (float4*)xB, NT);
    k_conv<<<(NT + 7) / 8, 256>>>((const float4*)xB, uioff, uicol, dinv, dinv, (float4*)xA, NT);
    k_conv<<<(NT + 7) / 8, 256>>>((const float4*)xA, uioff, uicol, dinv, dinv, (float4*)xB, NT);

    // ---- SSL prep + gathers ----
    k_sslprep<<<1024, 256>>>(user_idx, (const float4*)xB, 0, (const float4*)hu,
                             b1u, b2u, (float4*)embU, pos + 0);
    k_sslprep<<<1024, 256>>>(item_idx, (const float4*)xB, NU, (const float4*)hi,
                             b1i, b2i, (float4*)embI, pos + 2);
    k_gatherN<<<1024, 256>>>(neg_idx, (const float4*)xB, NU, (const float4*)hi, (float4*)embN);

    // ---- SSL alls via tensor cores (both sides, persistent + work stealing) ----
    k_alls_mma<<<296, 256, 69632>>>(b1u, b2u, b1i, b2i, alls, work);

    // ---- final transforms (only gathered rows) ----
    k_transform<<<BSZ / 8, 128>>>(embU, userW, userB, lng, lnb, out);
    k_transform<<<BSZ / 8, 128>>>(embI, itemW, itemB, lng, lnb, out + BD);
    k_transform<<<BSZ / 8, 128>>>(embN, itemW, itemB, lng, lnb, out + 2 * BD);

    // ---- loss scalar ----
    k_loss<<<1, 256>>>(alls, pos, out);
}

// round 8
// speedup vs baseline: 2.5692x; 1.7485x over previous
#include <cuda_runtime.h>
#include <cuda_bf16.h>
#include <cstdint>
#include <cstddef>
#include <math.h>

// ---------------- problem constants ----------------
constexpr int NU  = 40000;
constexpr int NI  = 40000;
constexpr int NT  = 80000;      // NU + NI
constexpr int D   = 128;
constexpr int EMP = 640000;
constexpr int EUI = 1600000;
constexpr int BSZ = 8192;
constexpr int BD  = BSZ * D;

// ---------------- device scratch (no allocs allowed) ----------------
__device__ float d_hu[NU * D];
__device__ float d_hi[NI * D];
__device__ float d_z0[NU * D];
__device__ float d_z1[NU * D];
__device__ float d_xA[NT * D];
__device__ float d_xB[NT * D];

__device__ int   d_mpcol[4 * EMP];
__device__ int   d_mpoff[4 * (NU + 1)];
__device__ int   d_mpcnt[4 * NU];     // dst counts
__device__ int   d_mpocnt[4 * NU];    // src counts
__device__ int   d_mpcur[4 * NU];
__device__ float d_oinv[4 * NU];
__device__ float d_iinv[4 * NU];

__device__ int   d_uicol[EUI];
__device__ int   d_uioff[NT + 1];
__device__ int   d_uicnt[NT];
__device__ int   d_uicur[NT];
__device__ float d_dinv[NT];

__device__ float d_S[12];     // attention score sums (2 per side-iter)
__device__ float d_pos[4];    // [0]=2*posdot sum U, [2]=2*posdot sum I
__device__ __nv_bfloat16 d_b1u[BD];
__device__ __nv_bfloat16 d_b2u[BD];
__device__ __nv_bfloat16 d_b1i[BD];
__device__ __nv_bfloat16 d_b2i[BD];
__device__ float d_embU[BD];
__device__ float d_embI[BD];
__device__ float d_embN[BD];
__device__ float d_alls[2 * BSZ];
__device__ int   d_work;

// ---------------- param structs (passed by value) ----------------
struct CntJobs  { const int* key[9]; int* cnt[9]; int n[9]; };
struct ScanJobs { const int* cnt[5]; int* off[5]; int n[5]; };
struct FillJobs { const int* key[5]; const int* val[5]; const int* off[5];
                  int* cur[5]; int* col[5]; int n[5]; };

// ---------------- helpers ----------------
__device__ __forceinline__ float warp_sum(float v) {
    #pragma unroll
    for (int d2 = 16; d2 > 0; d2 >>= 1) v += __shfl_down_sync(0xffffffffu, v, d2);
    return __shfl_sync(0xffffffffu, v, 0);
}
__device__ __forceinline__ float fast_tanh(float x) {
    float y; asm("tanh.approx.f32 %0, %1;" : "=f"(y) : "f"(x)); return y;
}
// cheap tanh: args in this model are ~N(0, 0.03); poly exact there, MUFU guard for tails
__device__ __forceinline__ float poly_tanh(float x) {
    float x2 = x * x;
    float t = x * fmaf(x2, fmaf(x2, 0.13333333f, -0.33333333f), 1.0f);
    if (fabsf(x) > 0.4f) t = fast_tanh(x);
    return t;
}
__device__ __forceinline__ void ldsm_x4(uint32_t& r0, uint32_t& r1, uint32_t& r2, uint32_t& r3,
                                        uint32_t addr) {
    asm volatile("ldmatrix.sync.aligned.m8n8.x4.shared.b16 {%0,%1,%2,%3}, [%4];"
        : "=r"(r0), "=r"(r1), "=r"(r2), "=r"(r3) : "r"(addr));
}
__device__ __forceinline__ void mma16816(float* c, const uint32_t* a, const uint32_t* b) {
    asm volatile("mma.sync.aligned.m16n8k16.row.col.f32.bf16.bf16.f32 "
        "{%0,%1,%2,%3},{%4,%5,%6,%7},{%8,%9},{%0,%1,%2,%3};"
        : "+f"(c[0]), "+f"(c[1]), "+f"(c[2]), "+f"(c[3])
        : "r"(a[0]), "r"(a[1]), "r"(a[2]), "r"(a[3]), "r"(b[0]), "r"(b[1]));
}
__device__ __forceinline__ uint32_t pk_bf16(float a, float b) {
    __nv_bfloat162 h = __float22bfloat162_rn(make_float2(a, b));
    return *(uint32_t*)&h;
}

// ---------------- structure kernels (fused) ----------------
__global__ void k_count9(CntJobs J) {
    int j = blockIdx.y;
    const int* a = J.key[j];
    int* cnt = J.cnt[j];
    int n = J.n[j];
    int i = blockIdx.x * blockDim.x + threadIdx.x, st = gridDim.x * blockDim.x;
    for (; i < n; i += st) atomicAdd(&cnt[a[i]], 1);
}
__global__ void k_inv_max1(const int* __restrict__ cnt, float* __restrict__ inv, int n) {
    int i = blockIdx.x * blockDim.x + threadIdx.x, st = gridDim.x * blockDim.x;
    for (; i < n; i += st) { int c = cnt[i]; inv[i] = rsqrtf((float)(c > 1 ? c : 1)); }
}
__global__ void k_inv_or0(const int* __restrict__ cnt, float* __restrict__ inv, int n) {
    int i = blockIdx.x * blockDim.x + threadIdx.x, st = gridDim.x * blockDim.x;
    for (; i < n; i += st) { int c = cnt[i]; inv[i] = (c > 0) ? rsqrtf((float)c) : 0.0f; }
}

// 5 independent single-block chunked exclusive scans
__global__ void k_scan5(ScanJobs J) {
    const int* cnt = J.cnt[blockIdx.x];
    int* off = J.off[blockIdx.x];
    int n = J.n[blockIdx.x];
    __shared__ int wsum[32];
    __shared__ int carry_s;
    int t = threadIdx.x, lane = t & 31, wid = t >> 5;
    if (t == 0) { carry_s = 0; off[0] = 0; }
    __syncthreads();
    for (int base = 0; base < n; base += 4096) {
        int idx0 = base + t * 4;
        int v0 = (idx0 + 0 < n) ? cnt[idx0 + 0] : 0;
        int v1 = (idx0 + 1 < n) ? cnt[idx0 + 1] : 0;
        int v2 = (idx0 + 2 < n) ? cnt[idx0 + 2] : 0;
        int v3 = (idx0 + 3 < n) ? cnt[idx0 + 3] : 0;
        v1 += v0; v2 += v1; v3 += v2;
        int ts = v3, sc = ts;
        #pragma unroll
        for (int d2 = 1; d2 < 32; d2 <<= 1) {
            int x = __shfl_up_sync(0xffffffffu, sc, d2);
            if (lane >= d2) sc += x;
        }
        if (lane == 31) wsum[wid] = sc;
        __syncthreads();
        if (wid == 0) {
            int s2 = wsum[lane];
            #pragma unroll
            for (int d2 = 1; d2 < 32; d2 <<= 1) {
                int x = __shfl_up_sync(0xffffffffu, s2, d2);
                if (lane >= d2) s2 += x;
            }
            wsum[lane] = s2;
        }
        __syncthreads();
        int woff = wid ? wsum[wid - 1] : 0;
        int b0 = carry_s + woff + (sc - ts);
        if (idx0 + 0 < n) off[idx0 + 1] = b0 + v0;
        if (idx0 + 1 < n) off[idx0 + 2] = b0 + v1;
        if (idx0 + 2 < n) off[idx0 + 3] = b0 + v2;
        if (idx0 + 3 < n) off[idx0 + 4] = b0 + v3;
        __syncthreads();
        if (t == 0) carry_s += wsum[31];
        __syncthreads();
    }
}

__global__ void k_fill5(FillJobs J) {
    int j = blockIdx.y;
    const int* key = J.key[j];
    const int* val = J.val[j];
    const int* off = J.off[j];
    int* cur = J.cur[j];
    int* col = J.col[j];
    int n = J.n[j];
    int i = blockIdx.x * blockDim.x + threadIdx.x, st = gridDim.x * blockDim.x;
    for (; i < n; i += st) {
        int k = key[i];
        col[off[k] + atomicAdd(&cur[k], 1)] = val[i];
    }
}

__global__ void k_copy_dual(const float4* __restrict__ s, float4* __restrict__ d1,
                            float4* __restrict__ d2, int n) {
    int i = blockIdx.x * blockDim.x + threadIdx.x, st = gridDim.x * blockDim.x;
    for (; i < n; i += st) { float4 v = s[i]; d1[i] = v; d2[i] = v; }
}

// ---------------- normalized graph conv: z[w] = dinv[w]*sum_{c in adj(w)} sinv[c]*h[c] ----------------
__global__ void k_conv(const float4* __restrict__ h, const int* __restrict__ off,
                       const int* __restrict__ col, const float* __restrict__ sinv,
                       const float* __restrict__ dinv, float4* __restrict__ z, int n) {
    int w = (blockIdx.x * blockDim.x + threadIdx.x) >> 5;
    int lane = threadIdx.x & 31;
    if (w >= n) return;
    int s = off[w], e = off[w + 1];
    float ax = 0.f, ay = 0.f, az = 0.f, aw = 0.f;
    for (int k = s; k < e; k++) {
        int c = col[k];
        float wt = sinv[c];
        float4 v = h[c * 32 + lane];
        ax = fmaf(wt, v.x, ax); ay = fmaf(wt, v.y, ay);
        az = fmaf(wt, v.z, az); aw = fmaf(wt, v.w, aw);
    }
    float di = dinv[w];
    z[w * 32 + lane] = make_float4(ax * di, ay * di, az * di, aw * di);
}

// ---------------- semantic attention via tensor cores ----------------
// S[p] += sum_rows tanh(Z_p @ W1 + b1) @ W2, p in {0,1}.
// Work unit = (tile of 128 rows, pipe). Block: 256 thr, 8 warps as 4(m) x 2(n),
// warp tile 32 x 64 processed in two 32-col halves. W1^T staged bf16 once per block.
__global__ void __launch_bounds__(256)
k_att_mma(const float* __restrict__ z0, const float* __restrict__ z1,
          const float* __restrict__ W1, const float* __restrict__ b1,
          const float* __restrict__ W2, float* __restrict__ S, int n) {
    extern __shared__ char sm[];
    char* sW = sm;                       // 128 * 272  (W1^T: row = out col n, k contiguous)
    char* sZ = sm + 34816;               // 128 * 272
    float* sB1 = (float*)(sm + 69632);   // 128
    float* sW2 = sB1 + 128;              // 128
    float* sred = sW2 + 128;             // 256
    int tid = threadIdx.x, lane = tid & 31, warp = tid >> 5;
    int warpM = warp >> 1, warpN = warp & 1;
    // stage W1 transposed -> bf16
    for (int i = tid; i < 16384; i += 256) {
        int k = i >> 7, nn = i & 127;
        *(__nv_bfloat16*)(sW + nn * 272 + k * 2) = __float2bfloat16(W1[i]);
    }
    if (tid < 128) { sB1[tid] = b1[tid]; sW2[tid] = W2[tid]; }
    uint32_t sWu = (uint32_t)__cvta_generic_to_shared(sW);
    uint32_t sZu = (uint32_t)__cvta_generic_to_shared(sZ);
    int ntiles = (n + 127) >> 7;
    float acc0 = 0.f, acc1 = 0.f;
    int q = lane >> 3, l7 = lane & 7;
    for (int unit = blockIdx.x; unit < 2 * ntiles; unit += gridDim.x) {
        int p = unit & 1, tile = unit >> 1;
        const float* Z = p ? z1 : z0;
        int i0 = tile << 7;
        __syncthreads();                  // protect sZ (and first-iter sW staging)
        for (int c = tid; c < 2048; c += 256) {
            int r = c >> 4, ch = c & 15;
            int row = i0 + r;
            uint4 v = make_uint4(0u, 0u, 0u, 0u);
            if (row < n) {
                const float* src = Z + row * 128 + ch * 8;
                float4 f0 = *(const float4*)src;
                float4 f1 = *(const float4*)(src + 4);
                v = make_uint4(pk_bf16(f0.x, f0.y), pk_bf16(f0.z, f0.w),
                               pk_bf16(f1.x, f1.y), pk_bf16(f1.z, f1.w));
            }
            *(uint4*)(sZ + r * 272 + ch * 16) = v;
        }
        __syncthreads();
        float unitAcc = 0.f;
        #pragma unroll
        for (int nh = 0; nh < 2; nh++) {
            float c_[2][4][4];
            #pragma unroll
            for (int mt = 0; mt < 2; mt++)
                #pragma unroll
                for (int nt = 0; nt < 4; nt++)
                    #pragma unroll
                    for (int e2 = 0; e2 < 4; e2++) c_[mt][nt][e2] = 0.f;
            #pragma unroll
            for (int ks = 0; ks < 8; ks++) {
                uint32_t af[2][4];
                uint32_t bfr[2][4];
                #pragma unroll
                for (int mt = 0; mt < 2; mt++) {
                    int row = warpM * 32 + mt * 16 + (q & 1) * 8 + l7;
                    int kc = ks * 16 + (q >> 1) * 8;
                    ldsm_x4(af[mt][0], af[mt][1], af[mt][2], af[mt][3],
                            sZu + row * 272 + kc * 2);
                }
                #pragma unroll
                for (int pp = 0; pp < 2; pp++) {
                    int colv = warpN * 64 + nh * 32 + pp * 16 + (q >> 1) * 8 + l7;
                    int kc = ks * 16 + (q & 1) * 8;
                    ldsm_x4(bfr[pp][0], bfr[pp][1], bfr[pp][2], bfr[pp][3],
                            sWu + colv * 272 + kc * 2);
                }
                #pragma unroll
                for (int mt = 0; mt < 2; mt++) {
                    mma16816(c_[mt][0], af[mt], &bfr[0][0]);
                    mma16816(c_[mt][1], af[mt], &bfr[0][2]);
                    mma16816(c_[mt][2], af[mt], &bfr[1][0]);
                    mma16816(c_[mt][3], af[mt], &bfr[1][2]);
                }
            }
            // epilogue: tanh(T + b1) * W2, masked by row < n
            #pragma unroll
            for (int mt = 0; mt < 2; mt++) {
                int rbase = i0 + warpM * 32 + mt * 16 + (lane >> 2);
                bool ok0 = (rbase < n), ok1 = (rbase + 8 < n);
                #pragma unroll
                for (int nt = 0; nt < 4; nt++) {
                    int col = warpN * 64 + nh * 32 + nt * 8 + (lane & 3) * 2;
                    float bA = sB1[col], bB = sB1[col + 1];
                    float wA = sW2[col], wB = sW2[col + 1];
                    if (ok0) unitAcc += poly_tanh(c_[mt][nt][0] + bA) * wA
                                      + poly_tanh(c_[mt][nt][1] + bB) * wB;
                    if (ok1) unitAcc += poly_tanh(c_[mt][nt][2] + bA) * wA
                                      + poly_tanh(c_[mt][nt][3] + bB) * wB;
                }
            }
        }
        if (p) acc1 += unitAcc; else acc0 += unitAcc;
    }
    __syncthreads();
    sred[tid] = acc0; __syncthreads();
    for (int d2 = 128; d2 > 0; d2 >>= 1) { if (tid < d2) sred[tid] += sred[tid + d2]; __syncthreads(); }
    if (tid == 0 && sred[0] != 0.f) atomicAdd(&S[0], sred[0]);
    if (tid == 0 && sred[0] == 0.f) atomicAdd(&S[0], 0.f);
    __syncthreads();
    sred[tid] = acc1; __syncthreads();
    for (int d2 = 128; d2 > 0; d2 >>= 1) { if (tid < d2) sred[tid] += sred[tid + d2]; __syncthreads(); }
    if (tid == 0) atomicAdd(&S[1], sred[0]);
}

// ---------------- h = beta0*z0 + beta1*z1, beta = softmax of means ----------------
__global__ void k_combine(const float4* __restrict__ z0, const float4* __restrict__ z1,
                          const float* __restrict__ S, float invn, float4* __restrict__ h, int n4) {
    float m0 = S[0] * invn, m1 = S[1] * invn;
    float b0 = 1.0f / (1.0f + expf(m1 - m0));
    float b1 = 1.0f - b0;
    int i = blockIdx.x * blockDim.x + threadIdx.x, st = gridDim.x * blockDim.x;
    for (; i < n4; i += st) {
        float4 a = z0[i], b = z1[i];
        h[i] = make_float4(b0 * a.x + b1 * b.x, b0 * a.y + b1 * b.y,
                           b0 * a.z + b1 * b.z, b0 * a.w + b1 * b.w);
    }
}

// ---------------- SSL prep: e1=x[idx], e2=0.5h+0.5e1; bf16 n1,n2; emb; 2*posdot ----------------
__global__ void k_sslprep(const int* __restrict__ idx, const float4* __restrict__ x, int xoff,
                          const float4* __restrict__ h, __nv_bfloat16* __restrict__ n1b,
                          __nv_bfloat16* __restrict__ n2b, float4* __restrict__ emb,
                          float* __restrict__ posAcc) {
    int b = (blockIdx.x * blockDim.x + threadIdx.x) >> 5;
    int lane = threadIdx.x & 31;
    if (b >= BSZ) return;
    int u = idx[b];
    float4 e1 = x[(xoff + u) * 32 + lane];
    float4 hv = h[u * 32 + lane];
    float4 e2 = make_float4(0.5f * (hv.x + e1.x), 0.5f * (hv.y + e1.y),
                            0.5f * (hv.z + e1.z), 0.5f * (hv.w + e1.w));
    float s11 = warp_sum(e1.x * e1.x + e1.y * e1.y + e1.z * e1.z + e1.w * e1.w);
    float s22 = warp_sum(e2.x * e2.x + e2.y * e2.y + e2.z * e2.z + e2.w * e2.w);
    float s12 = warp_sum(e1.x * e2.x + e1.y * e2.y + e1.z * e2.z + e1.w * e2.w);
    float inv1 = 1.0f / fmaxf(sqrtf(s11), 1e-12f);
    float inv2 = 1.0f / fmaxf(sqrtf(s22), 1e-12f);
    __nv_bfloat162* p1 = (__nv_bfloat162*)&n1b[b * 128 + lane * 4];
    p1[0] = __float22bfloat162_rn(make_float2(e1.x * inv1, e1.y * inv1));
    p1[1] = __float22bfloat162_rn(make_float2(e1.z * inv1, e1.w * inv1));
    __nv_bfloat162* p2 = (__nv_bfloat162*)&n2b[b * 128 + lane * 4];
    p2[0] = __float22bfloat162_rn(make_float2(e2.x * inv2, e2.y * inv2));
    p2[1] = __float22bfloat162_rn(make_float2(e2.z * inv2, e2.w * inv2));
    emb[b * 32 + lane] = e2;
    if (lane == 0) atomicAdd(posAcc, 2.0f * s12 * inv1 * inv2);
}

__global__ void k_gatherN(const int* __restrict__ idx, const float4* __restrict__ x, int xoff,
                          const float4* __restrict__ h, float4* __restrict__ emb) {
    int i = blockIdx.x * blockDim.x + threadIdx.x;
    if (i >= BSZ * 32) return;
    int b = i >> 5, lane = i & 31;
    int u = idx[b];
    float4 e1 = x[(xoff + u) * 32 + lane];
    float4 hv = h[u * 32 + lane];
    emb[i] = make_float4(0.5f * (hv.x + e1.x), 0.5f * (hv.y + e1.y),
                         0.5f * (hv.z + e1.z), 0.5f * (hv.w + e1.w));
}

// ---------------- alls[i] = sum_j exp(2 * n1_i . n2_j), tensor-core version ----------------
__global__ void __launch_bounds__(256, 2)
k_alls_mma(const __nv_bfloat16* __restrict__ n1u, const __nv_bfloat16* __restrict__ n2u,
           const __nv_bfloat16* __restrict__ n1i, const __nv_bfloat16* __restrict__ n2i,
           float* __restrict__ alls, int* __restrict__ work) {
    extern __shared__ char sm[];
    char* smA  = sm;             // 128 * 272 = 34816
    char* smB0 = sm + 34816;     // 64 * 272  = 17408
    char* smB1 = sm + 52224;
    __shared__ int s_unit;
    int tid = threadIdx.x;
    int lane = tid & 31, warp = tid >> 5;
    int warpM = warp >> 1, warpN = warp & 1;
    uint32_t smA_u  = (uint32_t)__cvta_generic_to_shared(smA);
    uint32_t smB0_u = (uint32_t)__cvta_generic_to_shared(smB0);
    uint32_t smB1_u = (uint32_t)__cvta_generic_to_shared(smB1);
    while (true) {
        __syncthreads();
        if (tid == 0) s_unit = atomicAdd(work, 1);
        __syncthreads();
        int u = s_unit;
        if (u >= 1024) return;
        int side = u >> 9;
        int rem = u & 511;
        int ib = rem >> 3, js = rem & 7;
        const __nv_bfloat16* A = side ? n1i : n1u;
        const __nv_bfloat16* B = side ? n2i : n2u;
        float* allsP = alls + side * BSZ;
        int i0 = ib * 128;
        #pragma unroll
        for (int i = 0; i < 8; i++) {
            int e = tid + 256 * i;
            int r = e >> 4, c = e & 15;
            uint4 v = *(const uint4*)((const char*)A + (i0 + r) * 256 + c * 16);
            *(uint4*)(smA + r * 272 + c * 16) = v;
        }
        float rs0 = 0.f, rs1 = 0.f, rs2 = 0.f, rs3 = 0.f;
        int j0 = js * 1024;
        uint4 pb[4];
        #pragma unroll
        for (int i = 0; i < 4; i++) {
            int e = tid + 256 * i;
            int r = e >> 4, c = e & 15;
            pb[i] = *(const uint4*)((const char*)B + (j0 + r) * 256 + c * 16);
        }
        for (int jt = 0; jt < 16; jt++) {
            int cur = jt & 1;
            char* sBw = cur ? smB1 : smB0;
            uint32_t sB = cur ? smB1_u : smB0_u;
            __syncthreads();
            #pragma unroll
            for (int i = 0; i < 4; i++) {
                int e = tid + 256 * i;
                int r = e >> 4, c = e & 15;
                *(uint4*)(sBw + r * 272 + c * 16) = pb[i];
            }
            if (jt < 15) {
                int jn = j0 + (jt + 1) * 64;
                #pragma unroll
                for (int i = 0; i < 4; i++) {
                    int e = tid + 256 * i;
                    int r = e >> 4, c = e & 15;
                    pb[i] = *(const uint4*)((const char*)B + (jn + r) * 256 + c * 16);
                }
            }
            __syncthreads();
            float c_[2][4][4];
            #pragma unroll
            for (int mt = 0; mt < 2; mt++)
                #pragma unroll
                for (int nt = 0; nt < 4; nt++)
                    #pragma unroll
                    for (int e2 = 0; e2 < 4; e2++) c_[mt][nt][e2] = 0.f;
            int q = lane >> 3, l7 = lane & 7;
            #pragma unroll
            for (int ks = 0; ks < 8; ks++) {
                uint32_t af[2][4];
                uint32_t bfr[2][4];
                #pragma unroll
                for (int mt = 0; mt < 2; mt++) {
                    int row = warpM * 32 + mt * 16 + (q & 1) * 8 + l7;
                    int kc = ks * 16 + (q >> 1) * 8;
                    ldsm_x4(af[mt][0], af[mt][1], af[mt][2], af[mt][3],
                            smA_u + row * 272 + kc * 2);
                }
                #pragma unroll
                for (int p = 0; p < 2; p++) {
                    int colv = warpN * 32 + p * 16 + (q >> 1) * 8 + l7;
                    int kc = ks * 16 + (q & 1) * 8;
                    ldsm_x4(bfr[p][0], bfr[p][1], bfr[p][2], bfr[p][3],
                            sB + colv * 272 + kc * 2);
                }
                #pragma unroll
                for (int mt = 0; mt < 2; mt++) {
                    mma16816(c_[mt][0], af[mt], &bfr[0][0]);
                    mma16816(c_[mt][1], af[mt], &bfr[0][2]);
                    mma16816(c_[mt][2], af[mt], &bfr[1][0]);
                    mma16816(c_[mt][3], af[mt], &bfr[1][2]);
                }
            }
            #pragma unroll
            for (int nt = 0; nt < 4; nt++) {
                rs0 += __expf(2.f * c_[0][nt][0]) + __expf(2.f * c_[0][nt][1]);
                rs1 += __expf(2.f * c_[0][nt][2]) + __expf(2.f * c_[0][nt][3]);
                rs2 += __expf(2.f * c_[1][nt][0]) + __expf(2.f * c_[1][nt][1]);
                rs3 += __expf(2.f * c_[1][nt][2]) + __expf(2.f * c_[1][nt][3]);
            }
        }
        #pragma unroll
        for (int d2 = 1; d2 <= 2; d2 <<= 1) {
            rs0 += __shfl_xor_sync(0xffffffffu, rs0, d2);
            rs1 += __shfl_xor_sync(0xffffffffu, rs1, d2);
            rs2 += __shfl_xor_sync(0xffffffffu, rs2, d2);
            rs3 += __shfl_xor_sync(0xffffffffu, rs3, d2);
        }
        if ((lane & 3) == 0) {
            int g = lane >> 2;
            int rb = i0 + warpM * 32;
            atomicAdd(&allsP[rb + g],      rs0);
            atomicAdd(&allsP[rb + 8 + g],  rs1);
            atomicAdd(&allsP[rb + 16 + g], rs2);
            atomicAdd(&allsP[rb + 24 + g], rs3);
        }
    }
}

// ---------------- final per-row transform: out = LN(relu(E @ W + b)) ----------------
__global__ void k_transform(const float* __restrict__ E, const float* __restrict__ W,
                            const float* __restrict__ bias, const float* __restrict__ g,
                            const float* __restrict__ bb, float* __restrict__ out) {
    __shared__ float sz[8][128];
    __shared__ float ys[8][129];
    int t = threadIdx.x;              // 128 threads; t = out column
    int r0 = blockIdx.x * 8;
    for (int e = t; e < 8 * 128; e += 128) sz[e >> 7][e & 127] = E[r0 * 128 + e];
    __syncthreads();
    float acc[8];
    float bv = bias[t];
    #pragma unroll
    for (int m = 0; m < 8; m++) acc[m] = bv;
    #pragma unroll 4
    for (int k = 0; k < 128; k++) {
        float wv = W[k * 128 + t];
        #pragma unroll
        for (int m = 0; m < 8; m++) acc[m] = fmaf(sz[m][k], wv, acc[m]);
    }
    #pragma unroll
    for (int m = 0; m < 8; m++) ys[m][t] = fmaxf(acc[m], 0.f);
    __syncthreads();
    int wid = t >> 5, lane = t & 31;
    for (int r = wid; r < 8; r += 4) {
        float s = 0.f;
        for (int k = lane; k < 128; k += 32) s += ys[r][k];
        s = warp_sum(s);
        float mu = s * (1.0f / 128.0f);
        float vs = 0.f;
        for (int k = lane; k < 128; k += 32) { float d = ys[r][k] - mu; vs += d * d; }
        vs = warp_sum(vs);
        float rstd = rsqrtf(vs * (1.0f / 128.0f) + 1e-5f);
        for (int k = lane; k < 128; k += 32)
            out[(r0 + r) * 128 + k] = (ys[r][k] - mu) * rstd * g[k] + bb[k];
    }
}

// ---------------- final loss scalar ----------------
__global__ void k_loss(const float* __restrict__ alls, const float* __restrict__ pos,
                       float* __restrict__ out) {
    __shared__ float red[256];
    int t = threadIdx.x;
    float s = 0.f;
    for (int i = t; i < 2 * BSZ; i += 256) s += logf(alls[i]);
    red[t] = s; __syncthreads();
    for (int d2 = 128; d2 > 0; d2 >>= 1) { if (t < d2) red[t] += red[t + d2]; __syncthreads(); }
    if (t == 0) out[3 * BD] = (0.4f / (float)BSZ) * (red[0] - pos[0] - pos[2]);
}

// ---------------- launch ----------------
extern "C" void kernel_launch(void* const* d_in, const int* in_sizes, int n_in,
                              void* d_out, int out_size) {
    const float* feat_u  = (const float*)d_in[0];
    const float* feat_i  = (const float*)d_in[1];
    const float* uW1 = (const float*)d_in[2];
    const float* ub1 = (const float*)d_in[3];
    const float* uW2 = (const float*)d_in[4];
    const float* iW1 = (const float*)d_in[5];
    const float* ib1 = (const float*)d_in[6];
    const float* iW2 = (const float*)d_in[7];
    const float* userW = (const float*)d_in[8];
    const float* userB = (const float*)d_in[9];
    const float* itemW = (const float*)d_in[10];
    const float* itemB = (const float*)d_in[11];
    const float* lng = (const float*)d_in[12];
    const float* lnb = (const float*)d_in[13];
    const int* mpsrc[4] = {(const int*)d_in[14], (const int*)d_in[16],
                           (const int*)d_in[18], (const int*)d_in[20]};
    const int* mpdst[4] = {(const int*)d_in[15], (const int*)d_in[17],
                           (const int*)d_in[19], (const int*)d_in[21]};
    const int* ui_row = (const int*)d_in[22];
    const int* ui_col = (const int*)d_in[23];
    const int* user_idx = (const int*)d_in[24];
    const int* item_idx = (const int*)d_in[25];
    const int* neg_idx  = (const int*)d_in[26];
    float* out = (float*)d_out;

    void* p_hu = 0;    void* p_hi = 0;    void* p_z0 = 0;    void* p_z1 = 0;
    void* p_xA = 0;    void* p_xB = 0;
    void* p_mpcol = 0; void* p_mpoff = 0; void* p_mpcnt = 0; void* p_mpocnt = 0;
    void* p_mpcur = 0; void* p_oinv = 0;  void* p_iinv = 0;
    void* p_uicol = 0; void* p_uioff = 0; void* p_uicnt = 0; void* p_uicur = 0;
    void* p_dinv = 0;
    void* p_S = 0;     void* p_pos = 0;
    void* p_b1u = 0;   void* p_b2u = 0;   void* p_b1i = 0;   void* p_b2i = 0;
    void* p_embU = 0;  void* p_embI = 0;  void* p_embN = 0;
    void* p_alls = 0;  void* p_work = 0;
    cudaGetSymbolAddress(&p_hu, d_hu);
    cudaGetSymbolAddress(&p_hi, d_hi);
    cudaGetSymbolAddress(&p_z0, d_z0);
    cudaGetSymbolAddress(&p_z1, d_z1);
    cudaGetSymbolAddress(&p_xA, d_xA);
    cudaGetSymbolAddress(&p_xB, d_xB);
    cudaGetSymbolAddress(&p_mpcol, d_mpcol);
    cudaGetSymbolAddress(&p_mpoff, d_mpoff);
    cudaGetSymbolAddress(&p_mpcnt, d_mpcnt);
    cudaGetSymbolAddress(&p_mpocnt, d_mpocnt);
    cudaGetSymbolAddress(&p_mpcur, d_mpcur);
    cudaGetSymbolAddress(&p_oinv, d_oinv);
    cudaGetSymbolAddress(&p_iinv, d_iinv);
    cudaGetSymbolAddress(&p_uicol, d_uicol);
    cudaGetSymbolAddress(&p_uioff, d_uioff);
    cudaGetSymbolAddress(&p_uicnt, d_uicnt);
    cudaGetSymbolAddress(&p_uicur, d_uicur);
    cudaGetSymbolAddress(&p_dinv, d_dinv);
    cudaGetSymbolAddress(&p_S, d_S);
    cudaGetSymbolAddress(&p_pos, d_pos);
    cudaGetSymbolAddress(&p_b1u, d_b1u);
    cudaGetSymbolAddress(&p_b2u, d_b2u);
    cudaGetSymbolAddress(&p_b1i, d_b1i);
    cudaGetSymbolAddress(&p_b2i, d_b2i);
    cudaGetSymbolAddress(&p_embU, d_embU);
    cudaGetSymbolAddress(&p_embI, d_embI);
    cudaGetSymbolAddress(&p_embN, d_embN);
    cudaGetSymbolAddress(&p_alls, d_alls);
    cudaGetSymbolAddress(&p_work, d_work);

    cudaFuncSetAttribute(k_att_mma, cudaFuncAttributeMaxDynamicSharedMemorySize, 71680);
    cudaFuncSetAttribute(k_alls_mma, cudaFuncAttributeMaxDynamicSharedMemorySize, 69632);

    float* hu = (float*)p_hu;
    float* hi = (float*)p_hi;
    float* z0 = (float*)p_z0;
    float* z1 = (float*)p_z1;
    float* xA = (float*)p_xA;
    float* xB = (float*)p_xB;
    int* mpcol = (int*)p_mpcol;
    int* mpoff = (int*)p_mpoff;
    int* mpcnt = (int*)p_mpcnt;
    int* mpocnt = (int*)p_mpocnt;
    int* mpcur = (int*)p_mpcur;
    float* oinv = (float*)p_oinv;
    float* iinv = (float*)p_iinv;
    int* uicol = (int*)p_uicol;
    int* uioff = (int*)p_uioff;
    int* uicnt = (int*)p_uicnt;
    int* uicur = (int*)p_uicur;
    float* dinv = (float*)p_dinv;
    float* S = (float*)p_S;
    float* pos = (float*)p_pos;
    __nv_bfloat16* b1u = (__nv_bfloat16*)p_b1u;
    __nv_bfloat16* b2u = (__nv_bfloat16*)p_b2u;
    __nv_bfloat16* b1i = (__nv_bfloat16*)p_b1i;
    __nv_bfloat16* b2i = (__nv_bfloat16*)p_b2i;
    float* embU = (float*)p_embU;
    float* embI = (float*)p_embI;
    float* embN = (float*)p_embN;
    float* alls = (float*)p_alls;
    int* work = (int*)p_work;

    // ---- zero per-call accumulators ----
    cudaMemsetAsync(p_mpcnt,  0, sizeof(int) * 4 * NU, 0);
    cudaMemsetAsync(p_mpocnt, 0, sizeof(int) * 4 * NU, 0);
    cudaMemsetAsync(p_mpcur,  0, sizeof(int) * 4 * NU, 0);
    cudaMemsetAsync(p_uicnt,  0, sizeof(int) * NT, 0);
    cudaMemsetAsync(p_uicur,  0, sizeof(int) * NT, 0);
    cudaMemsetAsync(p_S,    0, sizeof(float) * 12, 0);
    cudaMemsetAsync(p_pos,  0, sizeof(float) * 4, 0);
    cudaMemsetAsync(p_alls, 0, sizeof(float) * 2 * BSZ, 0);
    cudaMemsetAsync(p_work, 0, sizeof(int), 0);

    // ---- structure build (fused launches) ----
    CntJobs cj;
    for (int g = 0; g < 4; g++) {
        cj.key[g] = mpdst[g];     cj.cnt[g] = mpcnt + g * NU;   cj.n[g] = EMP;
        cj.key[4 + g] = mpsrc[g]; cj.cnt[4 + g] = mpocnt + g * NU; cj.n[4 + g] = EMP;
    }
    cj.key[8] = ui_row; cj.cnt[8] = uicnt; cj.n[8] = EUI;
    k_count9<<<dim3(256, 9), 256>>>(cj);

    ScanJobs sj;
    for (int g = 0; g < 4; g++) {
        sj.cnt[g] = mpcnt + g * NU; sj.off[g] = mpoff + g * (NU + 1); sj.n[g] = NU;
    }
    sj.cnt[4] = uicnt; sj.off[4] = uioff; sj.n[4] = NT;
    k_scan5<<<5, 1024>>>(sj);

    k_inv_max1<<<160, 256>>>(mpocnt, oinv, 4 * NU);
    k_inv_max1<<<160, 256>>>(mpcnt, iinv, 4 * NU);
    k_inv_or0<<<160, 256>>>(uicnt, dinv, NT);

    FillJobs fj;
    for (int g = 0; g < 4; g++) {
        fj.key[g] = mpdst[g]; fj.val[g] = mpsrc[g]; fj.off[g] = mpoff + g * (NU + 1);
        fj.cur[g] = mpcur + g * NU; fj.col[g] = mpcol + g * EMP; fj.n[g] = EMP;
    }
    fj.key[4] = ui_row; fj.val[4] = ui_col; fj.off[4] = uioff;
    fj.cur[4] = uicur; fj.col[4] = uicol; fj.n[4] = EUI;
    k_fill5<<<dim3(256, 5), 256>>>(fj);

    // ---- init h and x (read once, write twice) ----
    k_copy_dual<<<640, 256>>>((const float4*)feat_u, (float4*)hu, (float4*)xA, NU * 32);
    k_copy_dual<<<640, 256>>>((const float4*)feat_i, (float4*)hi, (float4*)(xA + NU * D), NI * 32);

    // ---- HAN: 3 iterations per side ----
    for (int side = 0; side < 2; side++) {
        float* h = side ? hi : hu;
        const float* W1 = side ? iW1 : uW1;
        const float* b1 = side ? ib1 : ub1;
        const float* W2 = side ? iW2 : uW2;
        int g0 = side * 2, g1 = side * 2 + 1;
        int n = side ? NI : NU;
        for (int it = 0; it < 3; it++) {
            k_conv<<<(n + 7) / 8, 256>>>((const float4*)h, mpoff + g0 * (NU + 1),
                mpcol + g0 * EMP, oinv + g0 * NU, iinv + g0 * NU, (float4*)z0, n);
            k_conv<<<(n + 7) / 8, 256>>>((const float4*)h, mpoff + g1 * (NU + 1),
                mpcol + g1 * EMP, oinv + g1 * NU, iinv + g1 * NU, (float4*)z1, n);
            float* Sp = S + 2 * (side * 3 + it);
            k_att_mma<<<296, 256, 71680>>>(z0, z1, W1, b1, W2, Sp, n);
            k_combine<<<512, 256>>>((const float4*)z0, (const float4*)z1, Sp,
                                    1.0f / (float)n, (float4*)h, n * 32);
        }
    }

    // ---- LightGCN: 3 hops on UI graph ----
    k_conv<<<(NT + 7) / 8, 256>>>((const float4*)xA, uioff, uicol, dinv, dinv, (float4*)xB, NT);
    k_conv<<<(NT + 7) / 8, 256>>>((const float4*)xB, uioff, uicol, dinv, dinv, (float4*)xA, NT);
    k_conv<<<(NT + 7) / 8, 256>>>((const float4*)xA, uioff, uicol, dinv, dinv, (float4*)xB, NT);

    // ---- SSL prep + gathers ----
    k_sslprep<<<1024, 256>>>(user_idx, (const float4*)xB, 0, (const float4*)hu,
                             b1u, b2u, (float4*)embU, pos + 0);
    k_sslprep<<<1024, 256>>>(item_idx, (const float4*)xB, NU, (const float4*)hi,
                             b1i, b2i, (float4*)embI, pos + 2);
    k_gatherN<<<1024, 256>>>(neg_idx, (const float4*)xB, NU, (const float4*)hi, (float4*)embN);

    // ---- SSL alls via tensor cores ----
    k_alls_mma<<<296, 256, 69632>>>(b1u, b2u, b1i, b2i, alls, work);

    // ---- final transforms (only gathered rows) ----
    k_transform<<<BSZ / 8, 128>>>(embU, userW, userB, lng, lnb, out);
    k_transform<<<BSZ / 8, 128>>>(embI, itemW, itemB, lng, lnb, out + BD);
    k_transform<<<BSZ / 8, 128>>>(embN, itemW, itemB, lng, lnb, out + 2 * BD);

    // ---- loss scalar ----
    k_loss<<<1, 256>>>(alls, pos, out);
}

// round 9
// speedup vs baseline: 2.6593x; 1.0350x over previous
#include <cuda_runtime.h>
#include <cuda_bf16.h>
#include <cstdint>
#include <cstddef>
#include <math.h>

// ---------------- problem constants ----------------
constexpr int NU  = 40000;
constexpr int NI  = 40000;
constexpr int NT  = 80000;      // NU + NI
constexpr int D   = 128;
constexpr int EMP = 640000;
constexpr int EUI = 1600000;
constexpr int BSZ = 8192;
constexpr int BD  = BSZ * D;

// ---------------- device scratch (no allocs allowed) ----------------
__device__ float d_hu[NU * D];
__device__ float d_hi[NI * D];
__device__ float d_z0u[NU * D];
__device__ float d_z1u[NU * D];
__device__ float d_z0i[NI * D];
__device__ float d_z1i[NI * D];
__device__ float d_xA[NT * D];
__device__ float d_xB[NT * D];

__device__ int   d_mpcol[4 * EMP];
__device__ int   d_mpoff[4 * (NU + 1)];
__device__ int   d_mpcnt[4 * NU];     // dst counts
__device__ int   d_mpocnt[4 * NU];    // src counts
__device__ int   d_mpcur[4 * NU];
__device__ float d_oinv[4 * NU];
__device__ float d_iinv[4 * NU];

__device__ int   d_uicol[EUI];
__device__ int   d_uioff[NT + 1];
__device__ int   d_uicnt[NT];
__device__ int   d_uicur[NT];
__device__ float d_dinv[NT];

__device__ float d_S[12];     // attention score sums (2 per side-iter)
__device__ float d_pos[4];    // [0]=2*posdot sum U, [2]=2*posdot sum I
__device__ __nv_bfloat16 d_b1u[BD];
__device__ __nv_bfloat16 d_b2u[BD];
__device__ __nv_bfloat16 d_b1i[BD];
__device__ __nv_bfloat16 d_b2i[BD];
__device__ float d_embU[BD];
__device__ float d_embI[BD];
__device__ float d_embN[BD];
__device__ float d_alls[2 * BSZ];
__device__ int   d_work;

// ---------------- param structs (passed by value) ----------------
struct CntJobs  { const int* key[9]; int* cnt[9]; int n[9]; };
struct ScanJobs { const int* cnt[5]; int* off[5]; int n[5]; };
struct FillJobs { const int* key[5]; const int* val[5]; const int* off[5];
                  int* cur[5]; int* col[5]; int n[5]; };
struct ZeroJobs { int* p[9]; int n[9]; };
struct ConvJobs { const float4* h[4]; const int* off[4]; const int* col[4];
                  const float* sinv[4]; const float* dinv[4]; float4* z[4]; };
struct AttJobs  { const float* z0[2]; const float* z1[2]; const float* W1[2];
                  const float* b1[2]; const float* W2[2]; float* S[2]; };
struct CmbJobs  { const float4* z0[2]; const float4* z1[2]; const float* S[2];
                  float4* h[2]; };

// ---------------- stream/event infra (created at load, outside checkpoints) ----------------
namespace {
struct HxStreams {
    cudaStream_t s1 = nullptr;
    cudaEvent_t eS = nullptr, eLG = nullptr, ePrep = nullptr, eT = nullptr;
    HxStreams() {
        if (cudaStreamCreateWithFlags(&s1, cudaStreamNonBlocking) != cudaSuccess) s1 = nullptr;
        cudaEventCreateWithFlags(&eS, cudaEventDisableTiming);
        cudaEventCreateWithFlags(&eLG, cudaEventDisableTiming);
        cudaEventCreateWithFlags(&ePrep, cudaEventDisableTiming);
        cudaEventCreateWithFlags(&eT, cudaEventDisableTiming);
    }
};
HxStreams g_hx;
}

// ---------------- helpers ----------------
__device__ __forceinline__ float warp_sum(float v) {
    #pragma unroll
    for (int d2 = 16; d2 > 0; d2 >>= 1) v += __shfl_down_sync(0xffffffffu, v, d2);
    return __shfl_sync(0xffffffffu, v, 0);
}
__device__ __forceinline__ float fast_tanh(float x) {
    float y; asm("tanh.approx.f32 %0, %1;" : "=f"(y) : "f"(x)); return y;
}
__device__ __forceinline__ float poly_tanh(float x) {
    float x2 = x * x;
    float t = x * fmaf(x2, fmaf(x2, 0.13333333f, -0.33333333f), 1.0f);
    if (fabsf(x) > 0.4f) t = fast_tanh(x);
    return t;
}
__device__ __forceinline__ void ldsm_x4(uint32_t& r0, uint32_t& r1, uint32_t& r2, uint32_t& r3,
                                        uint32_t addr) {
    asm volatile("ldmatrix.sync.aligned.m8n8.x4.shared.b16 {%0,%1,%2,%3}, [%4];"
        : "=r"(r0), "=r"(r1), "=r"(r2), "=r"(r3) : "r"(addr));
}
__device__ __forceinline__ void mma16816(float* c, const uint32_t* a, const uint32_t* b) {
    asm volatile("mma.sync.aligned.m16n8k16.row.col.f32.bf16.bf16.f32 "
        "{%0,%1,%2,%3},{%4,%5,%6,%7},{%8,%9},{%0,%1,%2,%3};"
        : "+f"(c[0]), "+f"(c[1]), "+f"(c[2]), "+f"(c[3])
        : "r"(a[0]), "r"(a[1]), "r"(a[2]), "r"(a[3]), "r"(b[0]), "r"(b[1]));
}
__device__ __forceinline__ uint32_t pk_bf16(float a, float b) {
    __nv_bfloat162 h = __float22bfloat162_rn(make_float2(a, b));
    return *(uint32_t*)&h;
}

// ---------------- structure kernels ----------------
__global__ void k_zero(ZeroJobs J) {
    int i = blockIdx.x * blockDim.x + threadIdx.x, st = gridDim.x * blockDim.x;
    #pragma unroll
    for (int s = 0; s < 9; s++) {
        int* p = J.p[s];
        int n = J.n[s];
        for (int k = i; k < n; k += st) p[k] = 0;
    }
}
__global__ void k_count9(CntJobs J) {
    int j = blockIdx.y;
    const int* a = J.key[j];
    int* cnt = J.cnt[j];
    int n = J.n[j];
    int i = blockIdx.x * blockDim.x + threadIdx.x, st = gridDim.x * blockDim.x;
    for (; i < n; i += st) atomicAdd(&cnt[a[i]], 1);
}
__global__ void k_inv_all(const int* __restrict__ mpocnt, const int* __restrict__ mpcnt,
                          const int* __restrict__ uicnt, float* __restrict__ oinv,
                          float* __restrict__ iinv, float* __restrict__ dinv) {
    int i = blockIdx.x * blockDim.x + threadIdx.x, st = gridDim.x * blockDim.x;
    int total = 4 * NU + 4 * NU + NT;
    for (; i < total; i += st) {
        if (i < 4 * NU) {
            int c = mpocnt[i]; oinv[i] = rsqrtf((float)(c > 1 ? c : 1));
        } else if (i < 8 * NU) {
            int c = mpcnt[i - 4 * NU]; iinv[i - 4 * NU] = rsqrtf((float)(c > 1 ? c : 1));
        } else {
            int c = uicnt[i - 8 * NU];
            dinv[i - 8 * NU] = (c > 0) ? rsqrtf((float)c) : 0.0f;
        }
    }
}

// 5 independent single-block chunked exclusive scans
__global__ void k_scan5(ScanJobs J) {
    const int* cnt = J.cnt[blockIdx.x];
    int* off = J.off[blockIdx.x];
    int n = J.n[blockIdx.x];
    __shared__ int wsum[32];
    __shared__ int carry_s;
    int t = threadIdx.x, lane = t & 31, wid = t >> 5;
    if (t == 0) { carry_s = 0; off[0] = 0; }
    __syncthreads();
    for (int base = 0; base < n; base += 4096) {
        int idx0 = base + t * 4;
        int v0 = (idx0 + 0 < n) ? cnt[idx0 + 0] : 0;
        int v1 = (idx0 + 1 < n) ? cnt[idx0 + 1] : 0;
        int v2 = (idx0 + 2 < n) ? cnt[idx0 + 2] : 0;
        int v3 = (idx0 + 3 < n) ? cnt[idx0 + 3] : 0;
        v1 += v0; v2 += v1; v3 += v2;
        int ts = v3, sc = ts;
        #pragma unroll
        for (int d2 = 1; d2 < 32; d2 <<= 1) {
            int x = __shfl_up_sync(0xffffffffu, sc, d2);
            if (lane >= d2) sc += x;
        }
        if (lane == 31) wsum[wid] = sc;
        __syncthreads();
        if (wid == 0) {
            int s2 = wsum[lane];
            #pragma unroll
            for (int d2 = 1; d2 < 32; d2 <<= 1) {
                int x = __shfl_up_sync(0xffffffffu, s2, d2);
                if (lane >= d2) s2 += x;
            }
            wsum[lane] = s2;
        }
        __syncthreads();
        int woff = wid ? wsum[wid - 1] : 0;
        int b0 = carry_s + woff + (sc - ts);
        if (idx0 + 0 < n) off[idx0 + 1] = b0 + v0;
        if (idx0 + 1 < n) off[idx0 + 2] = b0 + v1;
        if (idx0 + 2 < n) off[idx0 + 3] = b0 + v2;
        if (idx0 + 3 < n) off[idx0 + 4] = b0 + v3;
        __syncthreads();
        if (t == 0) carry_s += wsum[31];
        __syncthreads();
    }
}

__global__ void k_fill5(FillJobs J) {
    int j = blockIdx.y;
    const int* key = J.key[j];
    const int* val = J.val[j];
    const int* off = J.off[j];
    int* cur = J.cur[j];
    int* col = J.col[j];
    int n = J.n[j];
    int i = blockIdx.x * blockDim.x + threadIdx.x, st = gridDim.x * blockDim.x;
    for (; i < n; i += st) {
        int k = key[i];
        col[off[k] + atomicAdd(&cur[k], 1)] = val[i];
    }
}

__global__ void k_copy_dual(const float4* __restrict__ s, float4* __restrict__ d1,
                            float4* __restrict__ d2, int n) {
    int i = blockIdx.x * blockDim.x + threadIdx.x, st = gridDim.x * blockDim.x;
    for (; i < n; i += st) { float4 v = s[i]; d1[i] = v; d2[i] = v; }
}

// ---------------- normalized graph conv (single job, for LightGCN hops) ----------------
__global__ void k_conv(const float4* __restrict__ h, const int* __restrict__ off,
                       const int* __restrict__ col, const float* __restrict__ sinv,
                       const float* __restrict__ dinv, float4* __restrict__ z, int n) {
    int w = (blockIdx.x * blockDim.x + threadIdx.x) >> 5;
    int lane = threadIdx.x & 31;
    if (w >= n) return;
    int s = off[w], e = off[w + 1];
    float ax = 0.f, ay = 0.f, az = 0.f, aw = 0.f;
    for (int k = s; k < e; k++) {
        int c = col[k];
        float wt = sinv[c];
        float4 v = h[c * 32 + lane];
        ax = fmaf(wt, v.x, ax); ay = fmaf(wt, v.y, ay);
        az = fmaf(wt, v.z, az); aw = fmaf(wt, v.w, aw);
    }
    float di = dinv[w];
    z[w * 32 + lane] = make_float4(ax * di, ay * di, az * di, aw * di);
}

// ---------------- 4 metapath convs in one launch (blockIdx.y = job) ----------------
__global__ void k_conv4(ConvJobs J) {
    int j = blockIdx.y;
    const float4* h = J.h[j];
    const int* off = J.off[j];
    const int* col = J.col[j];
    const float* sinv = J.sinv[j];
    const float* dinv = J.dinv[j];
    float4* z = J.z[j];
    int w = (blockIdx.x * blockDim.x + threadIdx.x) >> 5;
    int lane = threadIdx.x & 31;
    if (w >= NU) return;
    int s = off[w], e = off[w + 1];
    float ax = 0.f, ay = 0.f, az = 0.f, aw = 0.f;
    for (int k = s; k < e; k++) {
        int c = col[k];
        float wt = sinv[c];
        float4 v = h[c * 32 + lane];
        ax = fmaf(wt, v.x, ax); ay = fmaf(wt, v.y, ay);
        az = fmaf(wt, v.z, az); aw = fmaf(wt, v.w, aw);
    }
    float di = dinv[w];
    z[w * 32 + lane] = make_float4(ax * di, ay * di, az * di, aw * di);
}

// ---------------- semantic attention (both sides) via tensor cores ----------------
__global__ void __launch_bounds__(256)
k_att2(AttJobs J) {
    int side = blockIdx.y;
    const float* z0 = J.z0[side];
    const float* z1 = J.z1[side];
    const float* W1 = J.W1[side];
    const float* b1 = J.b1[side];
    const float* W2 = J.W2[side];
    float* S = J.S[side];
    const int n = NU;
    extern __shared__ char sm[];
    char* sW = sm;                       // 128 * 272  (W1^T: row = out col, k contiguous)
    char* sZ = sm + 34816;               // 128 * 272
    float* sB1 = (float*)(sm + 69632);   // 128
    float* sW2 = sB1 + 128;              // 128
    float* sred = sW2 + 128;             // 256
    int tid = threadIdx.x, lane = tid & 31, warp = tid >> 5;
    int warpM = warp >> 1, warpN = warp & 1;
    for (int i = tid; i < 16384; i += 256) {
        int k = i >> 7, nn = i & 127;
        *(__nv_bfloat16*)(sW + nn * 272 + k * 2) = __float2bfloat16(W1[i]);
    }
    if (tid < 128) { sB1[tid] = b1[tid]; sW2[tid] = W2[tid]; }
    uint32_t sWu = (uint32_t)__cvta_generic_to_shared(sW);
    uint32_t sZu = (uint32_t)__cvta_generic_to_shared(sZ);
    int ntiles = (n + 127) >> 7;
    float acc0 = 0.f, acc1 = 0.f;
    int q = lane >> 3, l7 = lane & 7;
    for (int unit = blockIdx.x; unit < 2 * ntiles; unit += gridDim.x) {
        int p = unit & 1, tile = unit >> 1;
        const float* Z = p ? z1 : z0;
        int i0 = tile << 7;
        __syncthreads();
        for (int c = tid; c < 2048; c += 256) {
            int r = c >> 4, ch = c & 15;
            int row = i0 + r;
            uint4 v = make_uint4(0u, 0u, 0u, 0u);
            if (row < n) {
                const float* src = Z + row * 128 + ch * 8;
                float4 f0 = *(const float4*)src;
                float4 f1 = *(const float4*)(src + 4);
                v = make_uint4(pk_bf16(f0.x, f0.y), pk_bf16(f0.z, f0.w),
                               pk_bf16(f1.x, f1.y), pk_bf16(f1.z, f1.w));
            }
            *(uint4*)(sZ + r * 272 + ch * 16) = v;
        }
        __syncthreads();
        float unitAcc = 0.f;
        #pragma unroll
        for (int nh = 0; nh < 2; nh++) {
            float c_[2][4][4];
            #pragma unroll
            for (int mt = 0; mt < 2; mt++)
                #pragma unroll
                for (int nt = 0; nt < 4; nt++)
                    #pragma unroll
                    for (int e2 = 0; e2 < 4; e2++) c_[mt][nt][e2] = 0.f;
            #pragma unroll
            for (int ks = 0; ks < 8; ks++) {
                uint32_t af[2][4];
                uint32_t bfr[2][4];
                #pragma unroll
                for (int mt = 0; mt < 2; mt++) {
                    int row = warpM * 32 + mt * 16 + (q & 1) * 8 + l7;
                    int kc = ks * 16 + (q >> 1) * 8;
                    ldsm_x4(af[mt][0], af[mt][1], af[mt][2], af[mt][3],
                            sZu + row * 272 + kc * 2);
                }
                #pragma unroll
                for (int pp = 0; pp < 2; pp++) {
                    int colv = warpN * 64 + nh * 32 + pp * 16 + (q >> 1) * 8 + l7;
                    int kc = ks * 16 + (q & 1) * 8;
                    ldsm_x4(bfr[pp][0], bfr[pp][1], bfr[pp][2], bfr[pp][3],
                            sWu + colv * 272 + kc * 2);
                }
                #pragma unroll
                for (int mt = 0; mt < 2; mt++) {
                    mma16816(c_[mt][0], af[mt], &bfr[0][0]);
                    mma16816(c_[mt][1], af[mt], &bfr[0][2]);
                    mma16816(c_[mt][2], af[mt], &bfr[1][0]);
                    mma16816(c_[mt][3], af[mt], &bfr[1][2]);
                }
            }
            #pragma unroll
            for (int mt = 0; mt < 2; mt++) {
                int rbase = i0 + warpM * 32 + mt * 16 + (lane >> 2);
                bool ok0 = (rbase < n), ok1 = (rbase + 8 < n);
                #pragma unroll
                for (int nt = 0; nt < 4; nt++) {
                    int col = warpN * 64 + nh * 32 + nt * 8 + (lane & 3) * 2;
                    float bA = sB1[col], bB = sB1[col + 1];
                    float wA = sW2[col], wB = sW2[col + 1];
                    if (ok0) unitAcc += poly_tanh(c_[mt][nt][0] + bA) * wA
                                      + poly_tanh(c_[mt][nt][1] + bB) * wB;
                    if (ok1) unitAcc += poly_tanh(c_[mt][nt][2] + bA) * wA
                                      + poly_tanh(c_[mt][nt][3] + bB) * wB;
                }
            }
        }
        if (p) acc1 += unitAcc; else acc0 += unitAcc;
    }
    __syncthreads();
    sred[tid] = acc0; __syncthreads();
    for (int d2 = 128; d2 > 0; d2 >>= 1) { if (tid < d2) sred[tid] += sred[tid + d2]; __syncthreads(); }
    if (tid == 0) atomicAdd(&S[0], sred[0]);
    __syncthreads();
    sred[tid] = acc1; __syncthreads();
    for (int d2 = 128; d2 > 0; d2 >>= 1) { if (tid < d2) sred[tid] += sred[tid + d2]; __syncthreads(); }
    if (tid == 0) atomicAdd(&S[1], sred[0]);
}

// ---------------- h = beta0*z0 + beta1*z1 for both sides ----------------
__global__ void k_cmb2(CmbJobs J) {
    int side = blockIdx.y;
    const float4* z0 = J.z0[side];
    const float4* z1 = J.z1[side];
    const float* S = J.S[side];
    float4* h = J.h[side];
    const float invn = 1.0f / (float)NU;
    float m0 = S[0] * invn, m1 = S[1] * invn;
    float b0 = 1.0f / (1.0f + expf(m1 - m0));
    float b1 = 1.0f - b0;
    int n4 = NU * 32;
    int i = blockIdx.x * blockDim.x + threadIdx.x, st = gridDim.x * blockDim.x;
    for (; i < n4; i += st) {
        float4 a = z0[i], b = z1[i];
        h[i] = make_float4(b0 * a.x + b1 * b.x, b0 * a.y + b1 * b.y,
                           b0 * a.z + b1 * b.z, b0 * a.w + b1 * b.w);
    }
}

// ---------------- SSL prep (user, item, neg) in one launch ----------------
__global__ void k_prep3(const int* __restrict__ uidx, const int* __restrict__ iidx,
                        const int* __restrict__ nidx, const float4* __restrict__ xB,
                        const float4* __restrict__ hu, const float4* __restrict__ hi,
                        __nv_bfloat16* __restrict__ b1u, __nv_bfloat16* __restrict__ b2u,
                        __nv_bfloat16* __restrict__ b1i, __nv_bfloat16* __restrict__ b2i,
                        float4* __restrict__ embU, float4* __restrict__ embI,
                        float4* __restrict__ embN, float* __restrict__ pos) {
    int y = blockIdx.y;
    int gi = blockIdx.x * blockDim.x + threadIdx.x;
    int b = gi >> 5, lane = threadIdx.x & 31;
    if (b >= BSZ) return;
    if (y == 2) {
        int u = nidx[b];
        float4 e1 = xB[(NU + u) * 32 + lane];
        float4 hv = hi[u * 32 + lane];
        embN[b * 32 + lane] = make_float4(0.5f * (hv.x + e1.x), 0.5f * (hv.y + e1.y),
                                          0.5f * (hv.z + e1.z), 0.5f * (hv.w + e1.w));
        return;
    }
    const int* idx = y ? iidx : uidx;
    int xoff = y ? NU : 0;
    const float4* h = y ? hi : hu;
    __nv_bfloat16* n1b = y ? b1i : b1u;
    __nv_bfloat16* n2b = y ? b2i : b2u;
    float4* emb = y ? embI : embU;
    float* posAcc = pos + 2 * y;
    int u = idx[b];
    float4 e1 = xB[(xoff + u) * 32 + lane];
    float4 hv = h[u * 32 + lane];
    float4 e2 = make_float4(0.5f * (hv.x + e1.x), 0.5f * (hv.y + e1.y),
                            0.5f * (hv.z + e1.z), 0.5f * (hv.w + e1.w));
    float s11 = warp_sum(e1.x * e1.x + e1.y * e1.y + e1.z * e1.z + e1.w * e1.w);
    float s22 = warp_sum(e2.x * e2.x + e2.y * e2.y + e2.z * e2.z + e2.w * e2.w);
    float s12 = warp_sum(e1.x * e2.x + e1.y * e2.y + e1.z * e2.z + e1.w * e2.w);
    float inv1 = 1.0f / fmaxf(sqrtf(s11), 1e-12f);
    float inv2 = 1.0f / fmaxf(sqrtf(s22), 1e-12f);
    __nv_bfloat162* p1 = (__nv_bfloat162*)&n1b[b * 128 + lane * 4];
    p1[0] = __float22bfloat162_rn(make_float2(e1.x * inv1, e1.y * inv1));
    p1[1] = __float22bfloat162_rn(make_float2(e1.z * inv1, e1.w * inv1));
    __nv_bfloat162* p2 = (__nv_bfloat162*)&n2b[b * 128 + lane * 4];
    p2[0] = __float22bfloat162_rn(make_float2(e2.x * inv2, e2.y * inv2));
    p2[1] = __float22bfloat162_rn(make_float2(e2.z * inv2, e2.w * inv2));
    emb[b * 32 + lane] = e2;
    if (lane == 0) atomicAdd(posAcc, 2.0f * s12 * inv1 * inv2);
}

// ---------------- alls[i] = sum_j exp(2 * n1_i . n2_j), tensor-core version ----------------
__global__ void __launch_bounds__(256, 2)
k_alls_mma(const __nv_bfloat16* __restrict__ n1u, const __nv_bfloat16* __restrict__ n2u,
           const __nv_bfloat16* __restrict__ n1i, const __nv_bfloat16* __restrict__ n2i,
           float* __restrict__ alls, int* __restrict__ work) {
    extern __shared__ char sm[];
    char* smA  = sm;             // 128 * 272 = 34816
    char* smB0 = sm + 34816;     // 64 * 272  = 17408
    char* smB1 = sm + 52224;
    __shared__ int s_unit;
    int tid = threadIdx.x;
    int lane = tid & 31, warp = tid >> 5;
    int warpM = warp >> 1, warpN = warp & 1;
    uint32_t smA_u  = (uint32_t)__cvta_generic_to_shared(smA);
    uint32_t smB0_u = (uint32_t)__cvta_generic_to_shared(smB0);
    uint32_t smB1_u = (uint32_t)__cvta_generic_to_shared(smB1);
    while (true) {
        __syncthreads();
        if (tid == 0) s_unit = atomicAdd(work, 1);
        __syncthreads();
        int u = s_unit;
        if (u >= 1024) return;
        int side = u >> 9;
        int rem = u & 511;
        int ib = rem >> 3, js = rem & 7;
        const __nv_bfloat16* A = side ? n1i : n1u;
        const __nv_bfloat16* B = side ? n2i : n2u;
        float* allsP = alls + side * BSZ;
        int i0 = ib * 128;
        #pragma unroll
        for (int i = 0; i < 8; i++) {
            int e = tid + 256 * i;
            int r = e >> 4, c = e & 15;
            uint4 v = *(const uint4*)((const char*)A + (i0 + r) * 256 + c * 16);
            *(uint4*)(smA + r * 272 + c * 16) = v;
        }
        float rs0 = 0.f, rs1 = 0.f, rs2 = 0.f, rs3 = 0.f;
        int j0 = js * 1024;
        uint4 pb[4];
        #pragma unroll
        for (int i = 0; i < 4; i++) {
            int e = tid + 256 * i;
            int r = e >> 4, c = e & 15;
            pb[i] = *(const uint4*)((const char*)B + (j0 + r) * 256 + c * 16);
        }
        for (int jt = 0; jt < 16; jt++) {
            int cur = jt & 1;
            char* sBw = cur ? smB1 : smB0;
            uint32_t sB = cur ? smB1_u : smB0_u;
            __syncthreads();
            #pragma unroll
            for (int i = 0; i < 4; i++) {
                int e = tid + 256 * i;
                int r = e >> 4, c = e & 15;
                *(uint4*)(sBw + r * 272 + c * 16) = pb[i];
            }
            if (jt < 15) {
                int jn = j0 + (jt + 1) * 64;
                #pragma unroll
                for (int i = 0; i < 4; i++) {
                    int e = tid + 256 * i;
                    int r = e >> 4, c = e & 15;
                    pb[i] = *(const uint4*)((const char*)B + (jn + r) * 256 + c * 16);
                }
            }
            __syncthreads();
            float c_[2][4][4];
            #pragma unroll
            for (int mt = 0; mt < 2; mt++)
                #pragma unroll
                for (int nt = 0; nt < 4; nt++)
                    #pragma unroll
                    for (int e2 = 0; e2 < 4; e2++) c_[mt][nt][e2] = 0.f;
            int q = lane >> 3, l7 = lane & 7;
            #pragma unroll
            for (int ks = 0; ks < 8; ks++) {
                uint32_t af[2][4];
                uint32_t bfr[2][4];
                #pragma unroll
                for (int mt = 0; mt < 2; mt++) {
                    int row = warpM * 32 + mt * 16 + (q & 1) * 8 + l7;
                    int kc = ks * 16 + (q >> 1) * 8;
                    ldsm_x4(af[mt][0], af[mt][1], af[mt][2], af[mt][3],
                            smA_u + row * 272 + kc * 2);
                }
                #pragma unroll
                for (int p = 0; p < 2; p++) {
                    int colv = warpN * 32 + p * 16 + (q >> 1) * 8 + l7;
                    int kc = ks * 16 + (q & 1) * 8;
                    ldsm_x4(bfr[p][0], bfr[p][1], bfr[p][2], bfr[p][3],
                            sB + colv * 272 + kc * 2);
                }
                #pragma unroll
                for (int mt = 0; mt < 2; mt++) {
                    mma16816(c_[mt][0], af[mt], &bfr[0][0]);
                    mma16816(c_[mt][1], af[mt], &bfr[0][2]);
                    mma16816(c_[mt][2], af[mt], &bfr[1][0]);
                    mma16816(c_[mt][3], af[mt], &bfr[1][2]);
                }
            }
            #pragma unroll
            for (int nt = 0; nt < 4; nt++) {
                rs0 += __expf(2.f * c_[0][nt][0]) + __expf(2.f * c_[0][nt][1]);
                rs1 += __expf(2.f * c_[0][nt][2]) + __expf(2.f * c_[0][nt][3]);
                rs2 += __expf(2.f * c_[1][nt][0]) + __expf(2.f * c_[1][nt][1]);
                rs3 += __expf(2.f * c_[1][nt][2]) + __expf(2.f * c_[1][nt][3]);
            }
        }
        #pragma unroll
        for (int d2 = 1; d2 <= 2; d2 <<= 1) {
            rs0 += __shfl_xor_sync(0xffffffffu, rs0, d2);
            rs1 += __shfl_xor_sync(0xffffffffu, rs1, d2);
            rs2 += __shfl_xor_sync(0xffffffffu, rs2, d2);
            rs3 += __shfl_xor_sync(0xffffffffu, rs3, d2);
        }
        if ((lane & 3) == 0) {
            int g = lane >> 2;
            int rb = i0 + warpM * 32;
            atomicAdd(&allsP[rb + g],      rs0);
            atomicAdd(&allsP[rb + 8 + g],  rs1);
            atomicAdd(&allsP[rb + 16 + g], rs2);
            atomicAdd(&allsP[rb + 24 + g], rs3);
        }
    }
}

// ---------------- final per-row transforms (U, I, N) in one launch ----------------
__global__ void k_transform3(const float* __restrict__ embU, const float* __restrict__ embI,
                             const float* __restrict__ embN, const float* __restrict__ userW,
                             const float* __restrict__ userB, const float* __restrict__ itemW,
                             const float* __restrict__ itemB, const float* __restrict__ g,
                             const float* __restrict__ bb, float* __restrict__ out) {
    int y = blockIdx.y;
    const float* E = (y == 0) ? embU : ((y == 1) ? embI : embN);
    const float* W = (y == 0) ? userW : itemW;
    const float* bias = (y == 0) ? userB : itemB;
    float* o = out + y * BD;
    __shared__ float sz[8][128];
    __shared__ float ys[8][129];
    int t = threadIdx.x;
    int r0 = blockIdx.x * 8;
    for (int e = t; e < 8 * 128; e += 128) sz[e >> 7][e & 127] = E[r0 * 128 + e];
    __syncthreads();
    float acc[8];
    float bv = bias[t];
    #pragma unroll
    for (int m = 0; m < 8; m++) acc[m] = bv;
    #pragma unroll 4
    for (int k = 0; k < 128; k++) {
        float wv = W[k * 128 + t];
        #pragma unroll
        for (int m = 0; m < 8; m++) acc[m] = fmaf(sz[m][k], wv, acc[m]);
    }
    #pragma unroll
    for (int m = 0; m < 8; m++) ys[m][t] = fmaxf(acc[m], 0.f);
    __syncthreads();
    int wid = t >> 5, lane = t & 31;
    for (int r = wid; r < 8; r += 4) {
        float s = 0.f;
        for (int k = lane; k < 128; k += 32) s += ys[r][k];
        s = warp_sum(s);
        float mu = s * (1.0f / 128.0f);
        float vs = 0.f;
        for (int k = lane; k < 128; k += 32) { float d = ys[r][k] - mu; vs += d * d; }
        vs = warp_sum(vs);
        float rstd = rsqrtf(vs * (1.0f / 128.0f) + 1e-5f);
        for (int k = lane; k < 128; k += 32)
            o[(r0 + r) * 128 + k] = (ys[r][k] - mu) * rstd * g[k] + bb[k];
    }
}

// ---------------- final loss scalar ----------------
__global__ void k_loss(const float* __restrict__ alls, const float* __restrict__ pos,
                       float* __restrict__ out) {
    __shared__ float red[256];
    int t = threadIdx.x;
    float s = 0.f;
    for (int i = t; i < 2 * BSZ; i += 256) s += logf(alls[i]);
    red[t] = s; __syncthreads();
    for (int d2 = 128; d2 > 0; d2 >>= 1) { if (t < d2) red[t] += red[t + d2]; __syncthreads(); }
    if (t == 0) out[3 * BD] = (0.4f / (float)BSZ) * (red[0] - pos[0] - pos[2]);
}

// ---------------- launch ----------------
extern "C" void kernel_launch(void* const* d_in, const int* in_sizes, int n_in,
                              void* d_out, int out_size) {
    const float* feat_u  = (const float*)d_in[0];
    const float* feat_i  = (const float*)d_in[1];
    const float* uW1 = (const float*)d_in[2];
    const float* ub1 = (const float*)d_in[3];
    const float* uW2 = (const float*)d_in[4];
    const float* iW1 = (const float*)d_in[5];
    const float* ib1 = (const float*)d_in[6];
    const float* iW2 = (const float*)d_in[7];
    const float* userW = (const float*)d_in[8];
    const float* userB = (const float*)d_in[9];
    const float* itemW = (const float*)d_in[10];
    const float* itemB = (const float*)d_in[11];
    const float* lng = (const float*)d_in[12];
    const float* lnb = (const float*)d_in[13];
    const int* mpsrc[4] = {(const int*)d_in[14], (const int*)d_in[16],
                           (const int*)d_in[18], (const int*)d_in[20]};
    const int* mpdst[4] = {(const int*)d_in[15], (const int*)d_in[17],
                           (const int*)d_in[19], (const int*)d_in[21]};
    const int* ui_row = (const int*)d_in[22];
    const int* ui_col = (const int*)d_in[23];
    const int* user_idx = (const int*)d_in[24];
    const int* item_idx = (const int*)d_in[25];
    const int* neg_idx  = (const int*)d_in[26];
    float* out = (float*)d_out;

    void* p_hu = 0;    void* p_hi = 0;
    void* p_z0u = 0;   void* p_z1u = 0;  void* p_z0i = 0;  void* p_z1i = 0;
    void* p_xA = 0;    void* p_xB = 0;
    void* p_mpcol = 0; void* p_mpoff = 0; void* p_mpcnt = 0; void* p_mpocnt = 0;
    void* p_mpcur = 0; void* p_oinv = 0;  void* p_iinv = 0;
    void* p_uicol = 0; void* p_uioff = 0; void* p_uicnt = 0; void* p_uicur = 0;
    void* p_dinv = 0;
    void* p_S = 0;     void* p_pos = 0;
    void* p_b1u = 0;   void* p_b2u = 0;   void* p_b1i = 0;   void* p_b2i = 0;
    void* p_embU = 0;  void* p_embI = 0;  void* p_embN = 0;
    void* p_alls = 0;  void* p_work = 0;
    cudaGetSymbolAddress(&p_hu, d_hu);
    cudaGetSymbolAddress(&p_hi, d_hi);
    cudaGetSymbolAddress(&p_z0u, d_z0u);
    cudaGetSymbolAddress(&p_z1u, d_z1u);
    cudaGetSymbolAddress(&p_z0i, d_z0i);
    cudaGetSymbolAddress(&p_z1i, d_z1i);
    cudaGetSymbolAddress(&p_xA, d_xA);
    cudaGetSymbolAddress(&p_xB, d_xB);
    cudaGetSymbolAddress(&p_mpcol, d_mpcol);
    cudaGetSymbolAddress(&p_mpoff, d_mpoff);
    cudaGetSymbolAddress(&p_mpcnt, d_mpcnt);
    cudaGetSymbolAddress(&p_mpocnt, d_mpocnt);
    cudaGetSymbolAddress(&p_mpcur, d_mpcur);
    cudaGetSymbolAddress(&p_oinv, d_oinv);
    cudaGetSymbolAddress(&p_iinv, d_iinv);
    cudaGetSymbolAddress(&p_uicol, d_uicol);
    cudaGetSymbolAddress(&p_uioff, d_uioff);
    cudaGetSymbolAddress(&p_uicnt, d_uicnt);
    cudaGetSymbolAddress(&p_uicur, d_uicur);
    cudaGetSymbolAddress(&p_dinv, d_dinv);
    cudaGetSymbolAddress(&p_S, d_S);
    cudaGetSymbolAddress(&p_pos, d_pos);
    cudaGetSymbolAddress(&p_b1u, d_b1u);
    cudaGetSymbolAddress(&p_b2u, d_b2u);
    cudaGetSymbolAddress(&p_b1i, d_b1i);
    cudaGetSymbolAddress(&p_b2i, d_b2i);
    cudaGetSymbolAddress(&p_embU, d_embU);
    cudaGetSymbolAddress(&p_embI, d_embI);
    cudaGetSymbolAddress(&p_embN, d_embN);
    cudaGetSymbolAddress(&p_alls, d_alls);
    cudaGetSymbolAddress(&p_work, d_work);

    cudaFuncSetAttribute(k_att2, cudaFuncAttributeMaxDynamicSharedMemorySize, 71680);
    cudaFuncSetAttribute(k_alls_mma, cudaFuncAttributeMaxDynamicSharedMemorySize, 69632);

    float* hu = (float*)p_hu;
    float* hi = (float*)p_hi;
    float* z0u = (float*)p_z0u;
    float* z1u = (float*)p_z1u;
    float* z0i = (float*)p_z0i;
    float* z1i = (float*)p_z1i;
    float* xA = (float*)p_xA;
    float* xB = (float*)p_xB;
    int* mpcol = (int*)p_mpcol;
    int* mpoff = (int*)p_mpoff;
    int* mpcnt = (int*)p_mpcnt;
    int* mpocnt = (int*)p_mpocnt;
    int* mpcur = (int*)p_mpcur;
    float* oinv = (float*)p_oinv;
    float* iinv = (float*)p_iinv;
    int* uicol = (int*)p_uicol;
    int* uioff = (int*)p_uioff;
    int* uicnt = (int*)p_uicnt;
    int* uicur = (int*)p_uicur;
    float* dinv = (float*)p_dinv;
    float* S = (float*)p_S;
    float* pos = (float*)p_pos;
    __nv_bfloat16* b1u = (__nv_bfloat16*)p_b1u;
    __nv_bfloat16* b2u = (__nv_bfloat16*)p_b2u;
    __nv_bfloat16* b1i = (__nv_bfloat16*)p_b1i;
    __nv_bfloat16* b2i = (__nv_bfloat16*)p_b2i;
    float* embU = (float*)p_embU;
    float* embI = (float*)p_embI;
    float* embN = (float*)p_embN;
    float* alls = (float*)p_alls;
    int* work = (int*)p_work;

    bool useStreams = (g_hx.s1 != nullptr);

    // ---- zero per-call accumulators (one kernel) ----
    ZeroJobs zj;
    zj.p[0] = mpcnt;  zj.n[0] = 4 * NU;
    zj.p[1] = mpocnt; zj.n[1] = 4 * NU;
    zj.p[2] = mpcur;  zj.n[2] = 4 * NU;
    zj.p[3] = uicnt;  zj.n[3] = NT;
    zj.p[4] = uicur;  zj.n[4] = NT;
    zj.p[5] = (int*)alls; zj.n[5] = 2 * BSZ;
    zj.p[6] = (int*)S;    zj.n[6] = 12;
    zj.p[7] = (int*)pos;  zj.n[7] = 4;
    zj.p[8] = work;       zj.n[8] = 1;
    k_zero<<<160, 256>>>(zj);

    // ---- structure build ----
    CntJobs cj;
    for (int g = 0; g < 4; g++) {
        cj.key[g] = mpdst[g];     cj.cnt[g] = mpcnt + g * NU;      cj.n[g] = EMP;
        cj.key[4 + g] = mpsrc[g]; cj.cnt[4 + g] = mpocnt + g * NU; cj.n[4 + g] = EMP;
    }
    cj.key[8] = ui_row; cj.cnt[8] = uicnt; cj.n[8] = EUI;
    k_count9<<<dim3(256, 9), 256>>>(cj);

    ScanJobs sj;
    for (int g = 0; g < 4; g++) {
        sj.cnt[g] = mpcnt + g * NU; sj.off[g] = mpoff + g * (NU + 1); sj.n[g] = NU;
    }
    sj.cnt[4] = uicnt; sj.off[4] = uioff; sj.n[4] = NT;
    k_scan5<<<5, 1024>>>(sj);

    k_inv_all<<<400, 256>>>(mpocnt, mpcnt, uicnt, oinv, iinv, dinv);

    FillJobs fj;
    for (int g = 0; g < 4; g++) {
        fj.key[g] = mpdst[g]; fj.val[g] = mpsrc[g]; fj.off[g] = mpoff + g * (NU + 1);
        fj.cur[g] = mpcur + g * NU; fj.col[g] = mpcol + g * EMP; fj.n[g] = EMP;
    }
    fj.key[4] = ui_row; fj.val[4] = ui_col; fj.off[4] = uioff;
    fj.cur[4] = uicur; fj.col[4] = uicol; fj.n[4] = EUI;
    k_fill5<<<dim3(256, 5), 256>>>(fj);

    k_copy_dual<<<640, 256>>>((const float4*)feat_u, (float4*)hu, (float4*)xA, NU * 32);
    k_copy_dual<<<640, 256>>>((const float4*)feat_i, (float4*)hi, (float4*)(xA + NU * D), NI * 32);

    // ---- fork: LightGCN chain on side stream ----
    cudaStream_t sLG = useStreams ? g_hx.s1 : (cudaStream_t)0;
    if (useStreams) {
        cudaEventRecord(g_hx.eS, 0);
        cudaStreamWaitEvent(sLG, g_hx.eS, 0);
    }
    k_conv<<<(NT + 7) / 8, 256, 0, sLG>>>((const float4*)xA, uioff, uicol, dinv, dinv,
                                          (float4*)xB, NT);
    k_conv<<<(NT + 7) / 8, 256, 0, sLG>>>((const float4*)xB, uioff, uicol, dinv, dinv,
                                          (float4*)xA, NT);
    k_conv<<<(NT + 7) / 8, 256, 0, sLG>>>((const float4*)xA, uioff, uicol, dinv, dinv,
                                          (float4*)xB, NT);
    if (useStreams) cudaEventRecord(g_hx.eLG, sLG);

    // ---- HAN: 3 lockstep iterations, both sides per launch ----
    ConvJobs cvj;
    const float4* hs[4] = {(const float4*)hu, (const float4*)hu,
                           (const float4*)hi, (const float4*)hi};
    float4* zs[4] = {(float4*)z0u, (float4*)z1u, (float4*)z0i, (float4*)z1i};
    for (int j = 0; j < 4; j++) {
        cvj.h[j] = hs[j];
        cvj.off[j] = mpoff + j * (NU + 1);
        cvj.col[j] = mpcol + j * EMP;
        cvj.sinv[j] = oinv + j * NU;
        cvj.dinv[j] = iinv + j * NU;
        cvj.z[j] = zs[j];
    }
    AttJobs aj;
    aj.z0[0] = z0u; aj.z1[0] = z1u; aj.W1[0] = uW1; aj.b1[0] = ub1; aj.W2[0] = uW2;
    aj.z0[1] = z0i; aj.z1[1] = z1i; aj.W1[1] = iW1; aj.b1[1] = ib1; aj.W2[1] = iW2;
    CmbJobs mj;
    mj.z0[0] = (const float4*)z0u; mj.z1[0] = (const float4*)z1u; mj.h[0] = (float4*)hu;
    mj.z0[1] = (const float4*)z0i; mj.z1[1] = (const float4*)z1i; mj.h[1] = (float4*)hi;
    for (int it = 0; it < 3; it++) {
        k_conv4<<<dim3((NU + 7) / 8, 4), 256>>>(cvj);
        aj.S[0] = S + 2 * (0 * 3 + it);
        aj.S[1] = S + 2 * (1 * 3 + it);
        k_att2<<<dim3(148, 2), 256, 71680>>>(aj);
        mj.S[0] = aj.S[0];
        mj.S[1] = aj.S[1];
        k_cmb2<<<dim3(512, 2), 256>>>(mj);
    }

    // ---- join LightGCN, then SSL prep ----
    if (useStreams) cudaStreamWaitEvent(0, g_hx.eLG, 0);
    k_prep3<<<dim3(1024, 3), 256>>>(user_idx, item_idx, neg_idx, (const float4*)xB,
                                    (const float4*)hu, (const float4*)hi,
                                    b1u, b2u, b1i, b2i,
                                    (float4*)embU, (float4*)embI, (float4*)embN, pos);

    // ---- alls on default; transforms overlapped on side stream ----
    if (useStreams) {
        cudaEventRecord(g_hx.ePrep, 0);
        cudaStreamWaitEvent(g_hx.s1, g_hx.ePrep, 0);
        k_transform3<<<dim3(BSZ / 8, 3), 128, 0, g_hx.s1>>>(
            embU, embI, embN, userW, userB, itemW, itemB, lng, lnb, out);
        cudaEventRecord(g_hx.eT, g_hx.s1);
    } else {
        k_transform3<<<dim3(BSZ / 8, 3), 128>>>(
            embU, embI, embN, userW, userB, itemW, itemB, lng, lnb, out);
    }
    k_alls_mma<<<296, 256, 69632>>>(b1u, b2u, b1i, b2i, alls, work);
    k_loss<<<1, 256>>>(alls, pos, out);
    if (useStreams) cudaStreamWaitEvent(0, g_hx.eT, 0);   // re-join side stream
}